// round 10
// baseline (speedup 1.0000x reference)
#include <cuda_runtime.h>
#include <cuda_bf16.h>
#include <cuda_fp16.h>
#include <cstdint>

#define NTOK 8192
#define DH   128

// ---------------- scratch ----------------
__device__ __nv_bfloat16 g_qh[NTOK * DH];
__device__ __nv_bfloat16 g_ql[NTOK * DH];
__device__ __nv_bfloat16 g_kh[NTOK * DH];
__device__ __nv_bfloat16 g_kl[NTOK * DH];
__device__ __half g_vth[DH * NTOK];
__device__ float g_mp[2 * NTOK * DH];
__device__ float g_lp[4 * NTOK];       // [split][rs | m][row]
__device__ float g_h[NTOK * DH];

// ---------------- helpers ----------------
__device__ __forceinline__ uint32_t smem_u32(const void* p) {
    uint32_t a;
    asm("{ .reg .u64 t; cvta.to.shared.u64 t, %1; cvt.u32.u64 %0, t; }" : "=r"(a) : "l"(p));
    return a;
}
__device__ __forceinline__ void cpa16(uint32_t dst, const void* src) {
    asm volatile("cp.async.cg.shared.global [%0], [%1], 16;" :: "r"(dst), "l"(src));
}
__device__ __forceinline__ void cpa_commit() {
    asm volatile("cp.async.commit_group;" ::: "memory");
}
template <int N>
__device__ __forceinline__ void cpa_wait() {
    asm volatile("cp.async.wait_group %0;" :: "n"(N) : "memory");
}
__device__ __forceinline__ void ldm4(uint32_t addr, uint32_t r[4]) {
    asm volatile("ldmatrix.sync.aligned.m8n8.x4.shared.b16 {%0,%1,%2,%3}, [%4];"
                 : "=r"(r[0]), "=r"(r[1]), "=r"(r[2]), "=r"(r[3]) : "r"(addr));
}
__device__ __forceinline__ void mma_bf16(float c[4], uint32_t a0, uint32_t a1,
                                         uint32_t a2, uint32_t a3,
                                         uint32_t b0, uint32_t b1) {
    asm volatile("mma.sync.aligned.m16n8k16.row.col.f32.bf16.bf16.f32 "
                 "{%0,%1,%2,%3}, {%4,%5,%6,%7}, {%8,%9}, {%0,%1,%2,%3};"
                 : "+f"(c[0]), "+f"(c[1]), "+f"(c[2]), "+f"(c[3])
                 : "r"(a0), "r"(a1), "r"(a2), "r"(a3), "r"(b0), "r"(b1));
}
__device__ __forceinline__ void mma_f16(float c[4], uint32_t a0, uint32_t a1,
                                        uint32_t a2, uint32_t a3,
                                        uint32_t b0, uint32_t b1) {
    asm volatile("mma.sync.aligned.m16n8k16.row.col.f32.f16.f16.f32 "
                 "{%0,%1,%2,%3}, {%4,%5,%6,%7}, {%8,%9}, {%0,%1,%2,%3};"
                 : "+f"(c[0]), "+f"(c[1]), "+f"(c[2]), "+f"(c[3])
                 : "r"(a0), "r"(a1), "r"(a2), "r"(a3), "r"(b0), "r"(b1));
}
__device__ __forceinline__ uint32_t pkbf(float a, float b) {
    __nv_bfloat162 t = __floats2bfloat162_rn(a, b);
    return *reinterpret_cast<uint32_t*>(&t);
}

// ---------------- shared GEMM body: 32 rows x 128 cols per CTA ----------------
// 256 threads: tx = tid&15 (8 cols), ty = tid>>4 (2 rows). acc[2][8].
// As = smf[0..4096), Ws = smf[4096..20480). smem = 80 KB -> 2 CTAs/SM.
#define GSMEM (32 * 128 * 4 + 128 * 128 * 4)   // 81920

__device__ __forceinline__ void gemm32_body(
    const float* __restrict__ W, float* As, float* Ws,
    int tid, int tx, int ty, float acc[2][8])
{
    for (int idx = tid; idx < 128 * 32; idx += 256) {
        int row = idx >> 5, f4 = idx & 31;
        ((float4*)(Ws + row * 128))[f4] = ((const float4*)(W + row * 128))[f4];
    }
    __syncthreads();

#pragma unroll
    for (int i = 0; i < 2; i++)
#pragma unroll
        for (int j = 0; j < 8; j++) acc[i][j] = 0.f;

#pragma unroll 8
    for (int kk = 0; kk < 128; kk++) {
        float a0 = As[(ty * 2 + 0) * 128 + kk];
        float a1 = As[(ty * 2 + 1) * 128 + kk];
        float4 w0 = ((float4*)(Ws + kk * 128))[tx * 2];
        float4 w1 = ((float4*)(Ws + kk * 128))[tx * 2 + 1];
        acc[0][0] += a0 * w0.x; acc[0][1] += a0 * w0.y; acc[0][2] += a0 * w0.z; acc[0][3] += a0 * w0.w;
        acc[0][4] += a0 * w1.x; acc[0][5] += a0 * w1.y; acc[0][6] += a0 * w1.z; acc[0][7] += a0 * w1.w;
        acc[1][0] += a1 * w0.x; acc[1][1] += a1 * w0.y; acc[1][2] += a1 * w0.z; acc[1][3] += a1 * w0.w;
        acc[1][4] += a1 * w1.x; acc[1][5] += a1 * w1.y; acc[1][6] += a1 * w1.z; acc[1][7] += a1 * w1.w;
    }
}

// ---------------- fused QKV + convert: grid (256, 3) ----------------
__global__ void __launch_bounds__(256) qkv_kernel(
    const float* __restrict__ H,
    const float* __restrict__ Wq, const float* __restrict__ Wk, const float* __restrict__ Wv,
    __nv_bfloat16* __restrict__ qh, __nv_bfloat16* __restrict__ ql,
    __nv_bfloat16* __restrict__ kh, __nv_bfloat16* __restrict__ kl,
    __half* __restrict__ vth)
{
    extern __shared__ float smf[];
    float* As = smf;
    float* Ws = smf + 32 * 128;
    const int tid = threadIdx.x;
    const int tx = tid & 15, ty = tid >> 4;
    const int r0 = blockIdx.x * 32;
    const int w = blockIdx.y;

    for (int idx = tid; idx < 32 * 32; idx += 256) {
        int row = idx >> 5, f4 = idx & 31;
        ((float4*)(As + row * 128))[f4] = ((const float4*)(H + (size_t)(r0 + row) * 128))[f4];
    }

    const float* W = (w == 0) ? Wq : (w == 1) ? Wk : Wv;
    float acc[2][8];
    gemm32_body(W, As, Ws, tid, tx, ty, acc);

    if (w < 2) {
        __nv_bfloat16* dh = (w == 0) ? qh : kh;
        __nv_bfloat16* dl = (w == 0) ? ql : kl;
#pragma unroll
        for (int i = 0; i < 2; i++) {
            uint32_t hv[4], lv[4];
#pragma unroll
            for (int j = 0; j < 4; j++) {
                float v0 = acc[i][2 * j], v1 = acc[i][2 * j + 1];
                __nv_bfloat16 h0 = __float2bfloat16(v0), h1 = __float2bfloat16(v1);
                __nv_bfloat162 hp = __halves2bfloat162(h0, h1);
                hv[j] = *(uint32_t*)&hp;
                lv[j] = pkbf(v0 - __bfloat162float(h0), v1 - __bfloat162float(h1));
            }
            const size_t off = (size_t)(r0 + ty * 2 + i) * DH + tx * 8;
            *(uint4*)(dh + off) = make_uint4(hv[0], hv[1], hv[2], hv[3]);
            *(uint4*)(dl + off) = make_uint4(lv[0], lv[1], lv[2], lv[3]);
        }
    } else {
        // V transposed fp16 [d][t]: 2 consecutive t per 4-byte store
#pragma unroll
        for (int j = 0; j < 8; j++) {
            __half2 p = __floats2half2_rn(acc[0][j], acc[1][j]);
            *(uint32_t*)(vth + (size_t)(tx * 8 + j) * NTOK + r0 + ty * 2) = *(uint32_t*)&p;
        }
    }
}

// ---------------- fused attention (unchanged from R9) ----------------
#define KPAD 272
#define VPAD 144
#define STG_SZ 53248
#define SK_L   17408
#define SV_H   34816
#define ATT_SMEM (3 * STG_SZ)
#define MNEG  -1e30f
#define MINIT -1e29f

__global__ void __launch_bounds__(256, 1) attn_kernel(
    const __nv_bfloat16* __restrict__ qhg, const __nv_bfloat16* __restrict__ qlg,
    const __nv_bfloat16* __restrict__ khg, const __nv_bfloat16* __restrict__ klg,
    const __half* __restrict__ vthg,
    const int* __restrict__ adj, float* __restrict__ mp, float* __restrict__ lp)
{
    extern __shared__ char smc[];
    const uint32_t sb = smem_u32(smc);
    const int tid = threadIdx.x;
    const int wid = tid >> 5, lid = tid & 31;
    const int wrow = wid * 16;
    const int qbase = blockIdx.x * 128;
    const int split = blockIdx.y;
    const int tstart = split * (NTOK / 2);
    const int ntiles = (NTOK / 2) / 64;

    const int lrow = lid & 15, lcol = (lid >> 4) * 8;
    const uint32_t kbase = sb + lrow * KPAD + lcol * 2;
    const uint32_t vbase = sb + SV_H + lrow * VPAD + lcol * 2;

    const int fr0 = wrow + (lid >> 2);
    const int r0g = qbase + fr0;
    const int r1g = r0g + 8;
    const int cq = 2 * (lid & 3);

    uint32_t qfh[8][4], qfl[8][4];
    {
        const uint32_t qoff = sb + (wrow + lrow) * KPAD + lcol * 2;
#pragma unroll
        for (int i = 0; i < 8; i++) {
            const int idx = tid + i * 256;
            const int r = idx >> 4, c = idx & 15;
            cpa16(sb + r * KPAD + c * 16, qhg + (size_t)(qbase + r) * DH + c * 8);
        }
        cpa_commit(); cpa_wait<0>(); __syncthreads();
#pragma unroll
        for (int kc = 0; kc < 8; kc++) ldm4(qoff + kc * 32, qfh[kc]);
        __syncthreads();
#pragma unroll
        for (int i = 0; i < 8; i++) {
            const int idx = tid + i * 256;
            const int r = idx >> 4, c = idx & 15;
            cpa16(sb + r * KPAD + c * 16, qlg + (size_t)(qbase + r) * DH + c * 8);
        }
        cpa_commit(); cpa_wait<0>(); __syncthreads();
#pragma unroll
        for (int kc = 0; kc < 8; kc++) ldm4(qoff + kc * 32, qfl[kc]);
        __syncthreads();
    }

#define LOAD_STAGE(stg, T0)                                                              \
    do {                                                                                 \
        const uint32_t sbase = sb + (stg) * STG_SZ;                                      \
        _Pragma("unroll")                                                                \
        for (int i = 0; i < 4; i++) {                                                    \
            const int idx = tid + i * 256;                                               \
            const int r = idx >> 4, c = idx & 15;                                        \
            cpa16(sbase + r * KPAD + c * 16,        khg + (size_t)((T0) + r) * DH + c * 8); \
            cpa16(sbase + SK_L + r * KPAD + c * 16, klg + (size_t)((T0) + r) * DH + c * 8); \
        }                                                                                \
        _Pragma("unroll")                                                                \
        for (int i = 0; i < 4; i++) {                                                    \
            const int idx = tid + i * 256;                                               \
            const int r = idx >> 3, c = idx & 7;                                         \
            cpa16(sbase + SV_H + r * VPAD + c * 16, vthg + (size_t)r * NTOK + (T0) + c * 8); \
        }                                                                                \
        cpa_commit();                                                                    \
    } while (0)

    LOAD_STAGE(0, tstart);
    LOAD_STAGE(1, tstart + 64);

    float oacc[16][4];
#pragma unroll
    for (int i = 0; i < 16; i++)
#pragma unroll
        for (int j = 0; j < 4; j++) oacc[i][j] = 0.f;
    float rs0 = 0.f, rs1 = 0.f, m0 = MINIT, m1 = MINIT;

    int stage = 0;
    for (int it = 0; it < ntiles; it++) {
        const int t0 = tstart + it * 64;

        int2 av0[8], av1[8];
#pragma unroll
        for (int nb = 0; nb < 8; nb++) {
            const int col = t0 + nb * 8 + cq;
            av0[nb] = *(const int2*)(adj + (size_t)r0g * NTOK + col);
            av1[nb] = *(const int2*)(adj + (size_t)r1g * NTOK + col);
        }

        if (it + 2 < ntiles) { LOAD_STAGE((it + 2) % 3, t0 + 128); cpa_wait<2>(); }
        else if (it + 1 < ntiles) cpa_wait<1>();
        else cpa_wait<0>();
        __syncthreads();

        uint32_t mk = 0;
#pragma unroll
        for (int nb = 0; nb < 8; nb++) {
            mk |= (av0[nb].x > 0 ? 1u : 0u) << (2 * nb);
            mk |= (av0[nb].y > 0 ? 1u : 0u) << (2 * nb + 1);
            mk |= (av1[nb].x > 0 ? 1u : 0u) << (16 + 2 * nb);
            mk |= (av1[nb].y > 0 ? 1u : 0u) << (16 + 2 * nb + 1);
        }

        const uint32_t koff = kbase + stage * STG_SZ;
        const uint32_t voff = vbase + stage * STG_SZ;

        float sacc[8][4];
#pragma unroll
        for (int i = 0; i < 8; i++)
#pragma unroll
            for (int j = 0; j < 4; j++) sacc[i][j] = 0.f;

#pragma unroll
        for (int kc = 0; kc < 8; kc++) {
#pragma unroll
            for (int nb2 = 0; nb2 < 4; nb2++) {
                uint32_t kh[4], kl[4];
                ldm4(koff + nb2 * 16 * KPAD + kc * 32, kh);
                ldm4(koff + SK_L + nb2 * 16 * KPAD + kc * 32, kl);
                mma_bf16(sacc[2 * nb2],     qfh[kc][0], qfh[kc][1], qfh[kc][2], qfh[kc][3], kh[0], kh[2]);
                mma_bf16(sacc[2 * nb2 + 1], qfh[kc][0], qfh[kc][1], qfh[kc][2], qfh[kc][3], kh[1], kh[3]);
                mma_bf16(sacc[2 * nb2],     qfh[kc][0], qfh[kc][1], qfh[kc][2], qfh[kc][3], kl[0], kl[2]);
                mma_bf16(sacc[2 * nb2 + 1], qfh[kc][0], qfh[kc][1], qfh[kc][2], qfh[kc][3], kl[1], kl[3]);
                mma_bf16(sacc[2 * nb2],     qfl[kc][0], qfl[kc][1], qfl[kc][2], qfl[kc][3], kh[0], kh[2]);
                mma_bf16(sacc[2 * nb2 + 1], qfl[kc][0], qfl[kc][1], qfl[kc][2], qfl[kc][3], kh[1], kh[3]);
            }
        }

#pragma unroll
        for (int nb = 0; nb < 8; nb++) {
            if (!((mk >> (2 * nb)) & 1))      sacc[nb][0] = MNEG;
            if (!((mk >> (2 * nb + 1)) & 1))  sacc[nb][1] = MNEG;
            if (!((mk >> (16 + 2 * nb)) & 1)) sacc[nb][2] = MNEG;
            if (!((mk >> (17 + 2 * nb)) & 1)) sacc[nb][3] = MNEG;
        }
        float tm0 = MNEG, tm1 = MNEG;
#pragma unroll
        for (int nb = 0; nb < 8; nb++) {
            tm0 = fmaxf(tm0, fmaxf(sacc[nb][0], sacc[nb][1]));
            tm1 = fmaxf(tm1, fmaxf(sacc[nb][2], sacc[nb][3]));
        }
        tm0 = fmaxf(tm0, __shfl_xor_sync(0xffffffff, tm0, 1));
        tm0 = fmaxf(tm0, __shfl_xor_sync(0xffffffff, tm0, 2));
        tm1 = fmaxf(tm1, __shfl_xor_sync(0xffffffff, tm1, 1));
        tm1 = fmaxf(tm1, __shfl_xor_sync(0xffffffff, tm1, 2));
        if (tm0 > m0) {
            const float f = __expf(m0 - tm0);
            rs0 *= f;
#pragma unroll
            for (int db = 0; db < 16; db++) { oacc[db][0] *= f; oacc[db][1] *= f; }
            m0 = tm0;
        }
        if (tm1 > m1) {
            const float f = __expf(m1 - tm1);
            rs1 *= f;
#pragma unroll
            for (int db = 0; db < 16; db++) { oacc[db][2] *= f; oacc[db][3] *= f; }
            m1 = tm1;
        }

        uint32_t ph[8][2];
#pragma unroll
        for (int nb = 0; nb < 8; nb++) {
            float p00 = __expf(sacc[nb][0] - m0);
            float p01 = __expf(sacc[nb][1] - m0);
            float p10 = __expf(sacc[nb][2] - m1);
            float p11 = __expf(sacc[nb][3] - m1);
            __half2 h0 = __floats2half2_rn(p00, p01);
            __half2 h1 = __floats2half2_rn(p10, p11);
            ph[nb][0] = *(uint32_t*)&h0;
            ph[nb][1] = *(uint32_t*)&h1;
            float2 f0 = __half22float2(h0), f1 = __half22float2(h1);
            rs0 += f0.x + f0.y;
            rs1 += f1.x + f1.y;
        }

#pragma unroll
        for (int kc2 = 0; kc2 < 4; kc2++) {
            const uint32_t a0 = ph[2 * kc2][0], a1 = ph[2 * kc2][1];
            const uint32_t a2 = ph[2 * kc2 + 1][0], a3 = ph[2 * kc2 + 1][1];
#pragma unroll
            for (int db2 = 0; db2 < 8; db2++) {
                uint32_t vh[4];
                ldm4(voff + db2 * 16 * VPAD + kc2 * 32, vh);
                mma_f16(oacc[2 * db2],     a0, a1, a2, a3, vh[0], vh[2]);
                mma_f16(oacc[2 * db2 + 1], a0, a1, a2, a3, vh[1], vh[3]);
            }
        }
        __syncthreads();
        stage = (stage + 1) % 3;
    }

    rs0 += __shfl_xor_sync(0xffffffff, rs0, 1);
    rs0 += __shfl_xor_sync(0xffffffff, rs0, 2);
    rs1 += __shfl_xor_sync(0xffffffff, rs1, 1);
    rs1 += __shfl_xor_sync(0xffffffff, rs1, 2);
    if ((lid & 3) == 0) {
        lp[(size_t)split * 2 * NTOK + r0g] = rs0;
        lp[(size_t)split * 2 * NTOK + NTOK + r0g] = m0;
        lp[(size_t)split * 2 * NTOK + r1g] = rs1;
        lp[(size_t)split * 2 * NTOK + NTOK + r1g] = m1;
    }
    float* mp0 = mp + ((size_t)split * NTOK + r0g) * DH;
    float* mp1 = mp + ((size_t)split * NTOK + r1g) * DH;
#pragma unroll
    for (int db = 0; db < 16; db++) {
        const int c = db * 8 + cq;
        *(float2*)(mp0 + c) = make_float2(oacc[db][0], oacc[db][1]);
        *(float2*)(mp1 + c) = make_float2(oacc[db][2], oacc[db][3]);
    }
}

// ---------------- MLP layer 1 (fused split-combine), grid 256 ----------------
__global__ void __launch_bounds__(256) mlp1_kernel(
    const float* __restrict__ mp, const float* __restrict__ lp,
    const float* __restrict__ W, const float* __restrict__ bias, float* __restrict__ C)
{
    extern __shared__ float smf[];
    float* As = smf;
    float* Ws = smf + 32 * 128;
    const int tid = threadIdx.x;
    const int tx = tid & 15, ty = tid >> 4;
    const int r0 = blockIdx.x * 32;

    for (int idx = tid; idx < 32 * 32; idx += 256) {
        int row = idx >> 5, f4 = idx & 31;
        const int gr = r0 + row;
        const float l0 = lp[gr], mm0 = lp[NTOK + gr];
        const float l1 = lp[2 * NTOK + gr], mm1 = lp[3 * NTOK + gr];
        const float M = fmaxf(mm0, mm1);
        const float e0 = __expf(mm0 - M), e1 = __expf(mm1 - M);
        const float inv = 1.f / (l0 * e0 + l1 * e1);
        float4 a = ((const float4*)(mp + (size_t)gr * 128))[f4];
        float4 b = ((const float4*)(mp + (size_t)(NTOK + gr) * 128))[f4];
        float4 r;
        r.x = (a.x * e0 + b.x * e1) * inv;
        r.y = (a.y * e0 + b.y * e1) * inv;
        r.z = (a.z * e0 + b.z * e1) * inv;
        r.w = (a.w * e0 + b.w * e1) * inv;
        ((float4*)(As + row * 128))[f4] = r;
    }

    float acc[2][8];
    gemm32_body(W, As, Ws, tid, tx, ty, acc);

#pragma unroll
    for (int i = 0; i < 2; i++) {
        float* crow = C + (size_t)(r0 + ty * 2 + i) * 128 + tx * 8;
#pragma unroll
        for (int j = 0; j < 8; j++)
            crow[j] = fmaxf(acc[i][j] + bias[tx * 8 + j], 0.f);
    }
}

// ---------------- final MLP layer, grid 256 ----------------
__global__ void __launch_bounds__(256) gemm32_kernel(
    const float* __restrict__ A, const float* __restrict__ W,
    const float* __restrict__ bias, float* __restrict__ C)
{
    extern __shared__ float smf[];
    float* As = smf;
    float* Ws = smf + 32 * 128;
    const int tid = threadIdx.x;
    const int tx = tid & 15, ty = tid >> 4;
    const int r0 = blockIdx.x * 32;

    for (int idx = tid; idx < 32 * 32; idx += 256) {
        int row = idx >> 5, f4 = idx & 31;
        ((float4*)(As + row * 128))[f4] = ((const float4*)(A + (size_t)(r0 + row) * 128))[f4];
    }

    float acc[2][8];
    gemm32_body(W, As, Ws, tid, tx, ty, acc);

#pragma unroll
    for (int i = 0; i < 2; i++) {
        float* crow = C + (size_t)(r0 + ty * 2 + i) * 128 + tx * 8;
#pragma unroll
        for (int j = 0; j < 8; j++)
            crow[j] = fmaxf(acc[i][j] + bias[tx * 8 + j], 0.f);
    }
}

// ---------------- launch ----------------
extern "C" void kernel_launch(void* const* d_in, const int* in_sizes, int n_in,
                              void* d_out, int out_size)
{
    const float* H   = (const float*)d_in[0];
    const int*   adj = (const int*)d_in[1];
    const float* Wq  = (const float*)d_in[2];
    const float* Wk  = (const float*)d_in[3];
    const float* Wv  = (const float*)d_in[4];
    const float* W1  = (const float*)d_in[5];
    const float* b1  = (const float*)d_in[6];
    const float* W2  = (const float*)d_in[7];
    const float* b2  = (const float*)d_in[8];
    float* out = (float*)d_out;

    float *mpd, *lpd, *h;
    __nv_bfloat16 *qh, *ql, *kh, *kl;
    __half *vth;
    cudaGetSymbolAddress((void**)&qh,  g_qh);
    cudaGetSymbolAddress((void**)&ql,  g_ql);
    cudaGetSymbolAddress((void**)&kh,  g_kh);
    cudaGetSymbolAddress((void**)&kl,  g_kl);
    cudaGetSymbolAddress((void**)&vth, g_vth);
    cudaGetSymbolAddress((void**)&mpd, g_mp);
    cudaGetSymbolAddress((void**)&lpd, g_lp);
    cudaGetSymbolAddress((void**)&h,   g_h);

    cudaFuncSetAttribute(attn_kernel, cudaFuncAttributeMaxDynamicSharedMemorySize, ATT_SMEM);
    cudaFuncSetAttribute(qkv_kernel, cudaFuncAttributeMaxDynamicSharedMemorySize, GSMEM);
    cudaFuncSetAttribute(mlp1_kernel, cudaFuncAttributeMaxDynamicSharedMemorySize, GSMEM);
    cudaFuncSetAttribute(gemm32_kernel, cudaFuncAttributeMaxDynamicSharedMemorySize, GSMEM);

    qkv_kernel<<<dim3(NTOK / 32, 3), 256, GSMEM>>>(H, Wq, Wk, Wv, qh, ql, kh, kl, vth);

    attn_kernel<<<dim3(NTOK / 128, 2), 256, ATT_SMEM>>>(qh, ql, kh, kl, vth,
                                                        adj, mpd, lpd);

    mlp1_kernel<<<NTOK / 32, 256, GSMEM>>>(mpd, lpd, W1, b1, h);
    gemm32_kernel<<<NTOK / 32, 256, GSMEM>>>(h, W2, b2, out);
}

// round 12
// speedup vs baseline: 1.1239x; 1.1239x over previous
#include <cuda_runtime.h>
#include <cuda_bf16.h>
#include <cuda_fp16.h>
#include <cstdint>

#define NTOK 8192
#define DH   128

// ---------------- scratch ----------------
__device__ __nv_bfloat16 g_qh[NTOK * DH];
__device__ __nv_bfloat16 g_ql[NTOK * DH];
__device__ __nv_bfloat16 g_kh[NTOK * DH];
__device__ __nv_bfloat16 g_kl[NTOK * DH];
__device__ __half g_vth[DH * NTOK];
__device__ float g_mp[2 * NTOK * DH];
__device__ float g_lp[4 * NTOK];       // [split][rs | m][row]
__device__ float g_h[NTOK * DH];

// ---------------- helpers ----------------
__device__ __forceinline__ uint32_t smem_u32(const void* p) {
    uint32_t a;
    asm("{ .reg .u64 t; cvta.to.shared.u64 t, %1; cvt.u32.u64 %0, t; }" : "=r"(a) : "l"(p));
    return a;
}
__device__ __forceinline__ void cpa16(uint32_t dst, const void* src) {
    asm volatile("cp.async.cg.shared.global [%0], [%1], 16;" :: "r"(dst), "l"(src));
}
__device__ __forceinline__ void cpa_commit() {
    asm volatile("cp.async.commit_group;" ::: "memory");
}
template <int N>
__device__ __forceinline__ void cpa_wait() {
    asm volatile("cp.async.wait_group %0;" :: "n"(N) : "memory");
}
__device__ __forceinline__ void ldm4(uint32_t addr, uint32_t r[4]) {
    asm volatile("ldmatrix.sync.aligned.m8n8.x4.shared.b16 {%0,%1,%2,%3}, [%4];"
                 : "=r"(r[0]), "=r"(r[1]), "=r"(r[2]), "=r"(r[3]) : "r"(addr));
}
__device__ __forceinline__ void mma_bf16(float c[4], uint32_t a0, uint32_t a1,
                                         uint32_t a2, uint32_t a3,
                                         uint32_t b0, uint32_t b1) {
    asm volatile("mma.sync.aligned.m16n8k16.row.col.f32.bf16.bf16.f32 "
                 "{%0,%1,%2,%3}, {%4,%5,%6,%7}, {%8,%9}, {%0,%1,%2,%3};"
                 : "+f"(c[0]), "+f"(c[1]), "+f"(c[2]), "+f"(c[3])
                 : "r"(a0), "r"(a1), "r"(a2), "r"(a3), "r"(b0), "r"(b1));
}
__device__ __forceinline__ void mma_f16(float c[4], uint32_t a0, uint32_t a1,
                                        uint32_t a2, uint32_t a3,
                                        uint32_t b0, uint32_t b1) {
    asm volatile("mma.sync.aligned.m16n8k16.row.col.f32.f16.f16.f32 "
                 "{%0,%1,%2,%3}, {%4,%5,%6,%7}, {%8,%9}, {%0,%1,%2,%3};"
                 : "+f"(c[0]), "+f"(c[1]), "+f"(c[2]), "+f"(c[3])
                 : "r"(a0), "r"(a1), "r"(a2), "r"(a3), "r"(b0), "r"(b1));
}
__device__ __forceinline__ uint32_t pkbf(float a, float b) {
    __nv_bfloat162 t = __floats2bfloat162_rn(a, b);
    return *reinterpret_cast<uint32_t*>(&t);
}

// ---------------- GEMM body: 64 rows x 128 cols per CTA, 128 threads ----------------
// Thread (tx = tid&15 -> 8 cols, ry = tid>>4 -> 8 rows): 8x8 register tile.
// As [64][128] row-major (32 KB), Ws [128][128] row-major (64 KB) -> 96 KB, 2 CTAs/SM.
#define GSMEM (64 * 128 * 4 + 128 * 128 * 4)   // 98304

__device__ __forceinline__ void gemm64_body(
    const float* __restrict__ W, float* As, float* Ws,
    int tid, int tx, int ry, float acc[8][8])
{
    for (int idx = tid; idx < 128 * 32; idx += 128)
        ((float4*)Ws)[idx] = ((const float4*)W)[idx];
    __syncthreads();

#pragma unroll
    for (int i = 0; i < 8; i++)
#pragma unroll
        for (int j = 0; j < 8; j++) acc[i][j] = 0.f;

    const float* arow = As + ry * 8 * 128;
#pragma unroll 4
    for (int kk = 0; kk < 128; kk++) {
        float a[8];
#pragma unroll
        for (int i = 0; i < 8; i++) a[i] = arow[i * 128 + kk];
        float4 w0 = ((float4*)(Ws + kk * 128))[tx * 2];
        float4 w1 = ((float4*)(Ws + kk * 128))[tx * 2 + 1];
#pragma unroll
        for (int i = 0; i < 8; i++) {
            acc[i][0] += a[i] * w0.x; acc[i][1] += a[i] * w0.y;
            acc[i][2] += a[i] * w0.z; acc[i][3] += a[i] * w0.w;
            acc[i][4] += a[i] * w1.x; acc[i][5] += a[i] * w1.y;
            acc[i][6] += a[i] * w1.z; acc[i][7] += a[i] * w1.w;
        }
    }
}

// ---------------- fused QKV + convert: grid (128, 3), block 128 ----------------
__global__ void __launch_bounds__(128, 2) qkv_kernel(
    const float* __restrict__ H,
    const float* __restrict__ Wq, const float* __restrict__ Wk, const float* __restrict__ Wv,
    __nv_bfloat16* __restrict__ qh, __nv_bfloat16* __restrict__ ql,
    __nv_bfloat16* __restrict__ kh, __nv_bfloat16* __restrict__ kl,
    __half* __restrict__ vth)
{
    extern __shared__ float smf[];
    float* As = smf;
    float* Ws = smf + 64 * 128;
    const int tid = threadIdx.x;
    const int tx = tid & 15, ry = tid >> 4;
    const int r0 = blockIdx.x * 64;
    const int w = blockIdx.y;

    for (int idx = tid; idx < 64 * 32; idx += 128)
        ((float4*)As)[idx] = ((const float4*)(H + (size_t)r0 * 128))[idx];

    const float* W = (w == 0) ? Wq : (w == 1) ? Wk : Wv;
    float acc[8][8];
    gemm64_body(W, As, Ws, tid, tx, ry, acc);

    if (w < 2) {
        __nv_bfloat16* dh = (w == 0) ? qh : kh;
        __nv_bfloat16* dl = (w == 0) ? ql : kl;
#pragma unroll
        for (int i = 0; i < 8; i++) {
            uint32_t hv[4], lv[4];
#pragma unroll
            for (int j = 0; j < 4; j++) {
                float v0 = acc[i][2 * j], v1 = acc[i][2 * j + 1];
                __nv_bfloat16 h0 = __float2bfloat16(v0), h1 = __float2bfloat16(v1);
                __nv_bfloat162 hp = __halves2bfloat162(h0, h1);
                hv[j] = *(uint32_t*)&hp;
                lv[j] = pkbf(v0 - __bfloat162float(h0), v1 - __bfloat162float(h1));
            }
            const size_t off = (size_t)(r0 + ry * 8 + i) * DH + tx * 8;
            *(uint4*)(dh + off) = make_uint4(hv[0], hv[1], hv[2], hv[3]);
            *(uint4*)(dl + off) = make_uint4(lv[0], lv[1], lv[2], lv[3]);
        }
    } else {
        // V transposed fp16 [d][t]: thread owns 8 consecutive t per column j
#pragma unroll
        for (int j = 0; j < 8; j++) {
            __half2 p0 = __floats2half2_rn(acc[0][j], acc[1][j]);
            __half2 p1 = __floats2half2_rn(acc[2][j], acc[3][j]);
            __half2 p2 = __floats2half2_rn(acc[4][j], acc[5][j]);
            __half2 p3 = __floats2half2_rn(acc[6][j], acc[7][j]);
            *(uint4*)(vth + (size_t)(tx * 8 + j) * NTOK + r0 + ry * 8) =
                make_uint4(*(uint32_t*)&p0, *(uint32_t*)&p1,
                           *(uint32_t*)&p2, *(uint32_t*)&p3);
        }
    }
}

// ---------------- fused attention (unchanged from R9 best) ----------------
#define KPAD 272
#define VPAD 144
#define STG_SZ 53248
#define SK_L   17408
#define SV_H   34816
#define ATT_SMEM (3 * STG_SZ)
#define MNEG  -1e30f
#define MINIT -1e29f

__global__ void __launch_bounds__(256, 1) attn_kernel(
    const __nv_bfloat16* __restrict__ qhg, const __nv_bfloat16* __restrict__ qlg,
    const __nv_bfloat16* __restrict__ khg, const __nv_bfloat16* __restrict__ klg,
    const __half* __restrict__ vthg,
    const int* __restrict__ adj, float* __restrict__ mp, float* __restrict__ lp)
{
    extern __shared__ char smc[];
    const uint32_t sb = smem_u32(smc);
    const int tid = threadIdx.x;
    const int wid = tid >> 5, lid = tid & 31;
    const int wrow = wid * 16;
    const int qbase = blockIdx.x * 128;
    const int split = blockIdx.y;
    const int tstart = split * (NTOK / 2);
    const int ntiles = (NTOK / 2) / 64;

    const int lrow = lid & 15, lcol = (lid >> 4) * 8;
    const uint32_t kbase = sb + lrow * KPAD + lcol * 2;
    const uint32_t vbase = sb + SV_H + lrow * VPAD + lcol * 2;

    const int fr0 = wrow + (lid >> 2);
    const int r0g = qbase + fr0;
    const int r1g = r0g + 8;
    const int cq = 2 * (lid & 3);

    uint32_t qfh[8][4], qfl[8][4];
    {
        const uint32_t qoff = sb + (wrow + lrow) * KPAD + lcol * 2;
#pragma unroll
        for (int i = 0; i < 8; i++) {
            const int idx = tid + i * 256;
            const int r = idx >> 4, c = idx & 15;
            cpa16(sb + r * KPAD + c * 16, qhg + (size_t)(qbase + r) * DH + c * 8);
        }
        cpa_commit(); cpa_wait<0>(); __syncthreads();
#pragma unroll
        for (int kc = 0; kc < 8; kc++) ldm4(qoff + kc * 32, qfh[kc]);
        __syncthreads();
#pragma unroll
        for (int i = 0; i < 8; i++) {
            const int idx = tid + i * 256;
            const int r = idx >> 4, c = idx & 15;
            cpa16(sb + r * KPAD + c * 16, qlg + (size_t)(qbase + r) * DH + c * 8);
        }
        cpa_commit(); cpa_wait<0>(); __syncthreads();
#pragma unroll
        for (int kc = 0; kc < 8; kc++) ldm4(qoff + kc * 32, qfl[kc]);
        __syncthreads();
    }

#define LOAD_STAGE(stg, T0)                                                              \
    do {                                                                                 \
        const uint32_t sbase = sb + (stg) * STG_SZ;                                      \
        _Pragma("unroll")                                                                \
        for (int i = 0; i < 4; i++) {                                                    \
            const int idx = tid + i * 256;                                               \
            const int r = idx >> 4, c = idx & 15;                                        \
            cpa16(sbase + r * KPAD + c * 16,        khg + (size_t)((T0) + r) * DH + c * 8); \
            cpa16(sbase + SK_L + r * KPAD + c * 16, klg + (size_t)((T0) + r) * DH + c * 8); \
        }                                                                                \
        _Pragma("unroll")                                                                \
        for (int i = 0; i < 4; i++) {                                                    \
            const int idx = tid + i * 256;                                               \
            const int r = idx >> 3, c = idx & 7;                                         \
            cpa16(sbase + SV_H + r * VPAD + c * 16, vthg + (size_t)r * NTOK + (T0) + c * 8); \
        }                                                                                \
        cpa_commit();                                                                    \
    } while (0)

    LOAD_STAGE(0, tstart);
    LOAD_STAGE(1, tstart + 64);

    float oacc[16][4];
#pragma unroll
    for (int i = 0; i < 16; i++)
#pragma unroll
        for (int j = 0; j < 4; j++) oacc[i][j] = 0.f;
    float rs0 = 0.f, rs1 = 0.f, m0 = MINIT, m1 = MINIT;

    int stage = 0;
    for (int it = 0; it < ntiles; it++) {
        const int t0 = tstart + it * 64;

        int2 av0[8], av1[8];
#pragma unroll
        for (int nb = 0; nb < 8; nb++) {
            const int col = t0 + nb * 8 + cq;
            av0[nb] = *(const int2*)(adj + (size_t)r0g * NTOK + col);
            av1[nb] = *(const int2*)(adj + (size_t)r1g * NTOK + col);
        }

        if (it + 2 < ntiles) { LOAD_STAGE((it + 2) % 3, t0 + 128); cpa_wait<2>(); }
        else if (it + 1 < ntiles) cpa_wait<1>();
        else cpa_wait<0>();
        __syncthreads();

        uint32_t mk = 0;
#pragma unroll
        for (int nb = 0; nb < 8; nb++) {
            mk |= (av0[nb].x > 0 ? 1u : 0u) << (2 * nb);
            mk |= (av0[nb].y > 0 ? 1u : 0u) << (2 * nb + 1);
            mk |= (av1[nb].x > 0 ? 1u : 0u) << (16 + 2 * nb);
            mk |= (av1[nb].y > 0 ? 1u : 0u) << (16 + 2 * nb + 1);
        }

        const uint32_t koff = kbase + stage * STG_SZ;
        const uint32_t voff = vbase + stage * STG_SZ;

        float sacc[8][4];
#pragma unroll
        for (int i = 0; i < 8; i++)
#pragma unroll
            for (int j = 0; j < 4; j++) sacc[i][j] = 0.f;

#pragma unroll
        for (int kc = 0; kc < 8; kc++) {
#pragma unroll
            for (int nb2 = 0; nb2 < 4; nb2++) {
                uint32_t kh[4], kl[4];
                ldm4(koff + nb2 * 16 * KPAD + kc * 32, kh);
                ldm4(koff + SK_L + nb2 * 16 * KPAD + kc * 32, kl);
                mma_bf16(sacc[2 * nb2],     qfh[kc][0], qfh[kc][1], qfh[kc][2], qfh[kc][3], kh[0], kh[2]);
                mma_bf16(sacc[2 * nb2 + 1], qfh[kc][0], qfh[kc][1], qfh[kc][2], qfh[kc][3], kh[1], kh[3]);
                mma_bf16(sacc[2 * nb2],     qfh[kc][0], qfh[kc][1], qfh[kc][2], qfh[kc][3], kl[0], kl[2]);
                mma_bf16(sacc[2 * nb2 + 1], qfh[kc][0], qfh[kc][1], qfh[kc][2], qfh[kc][3], kl[1], kl[3]);
                mma_bf16(sacc[2 * nb2],     qfl[kc][0], qfl[kc][1], qfl[kc][2], qfl[kc][3], kh[0], kh[2]);
                mma_bf16(sacc[2 * nb2 + 1], qfl[kc][0], qfl[kc][1], qfl[kc][2], qfl[kc][3], kh[1], kh[3]);
            }
        }

#pragma unroll
        for (int nb = 0; nb < 8; nb++) {
            if (!((mk >> (2 * nb)) & 1))      sacc[nb][0] = MNEG;
            if (!((mk >> (2 * nb + 1)) & 1))  sacc[nb][1] = MNEG;
            if (!((mk >> (16 + 2 * nb)) & 1)) sacc[nb][2] = MNEG;
            if (!((mk >> (17 + 2 * nb)) & 1)) sacc[nb][3] = MNEG;
        }
        float tm0 = MNEG, tm1 = MNEG;
#pragma unroll
        for (int nb = 0; nb < 8; nb++) {
            tm0 = fmaxf(tm0, fmaxf(sacc[nb][0], sacc[nb][1]));
            tm1 = fmaxf(tm1, fmaxf(sacc[nb][2], sacc[nb][3]));
        }
        tm0 = fmaxf(tm0, __shfl_xor_sync(0xffffffff, tm0, 1));
        tm0 = fmaxf(tm0, __shfl_xor_sync(0xffffffff, tm0, 2));
        tm1 = fmaxf(tm1, __shfl_xor_sync(0xffffffff, tm1, 1));
        tm1 = fmaxf(tm1, __shfl_xor_sync(0xffffffff, tm1, 2));
        if (tm0 > m0) {
            const float f = __expf(m0 - tm0);
            rs0 *= f;
#pragma unroll
            for (int db = 0; db < 16; db++) { oacc[db][0] *= f; oacc[db][1] *= f; }
            m0 = tm0;
        }
        if (tm1 > m1) {
            const float f = __expf(m1 - tm1);
            rs1 *= f;
#pragma unroll
            for (int db = 0; db < 16; db++) { oacc[db][2] *= f; oacc[db][3] *= f; }
            m1 = tm1;
        }

        uint32_t ph[8][2];
#pragma unroll
        for (int nb = 0; nb < 8; nb++) {
            float p00 = __expf(sacc[nb][0] - m0);
            float p01 = __expf(sacc[nb][1] - m0);
            float p10 = __expf(sacc[nb][2] - m1);
            float p11 = __expf(sacc[nb][3] - m1);
            __half2 h0 = __floats2half2_rn(p00, p01);
            __half2 h1 = __floats2half2_rn(p10, p11);
            ph[nb][0] = *(uint32_t*)&h0;
            ph[nb][1] = *(uint32_t*)&h1;
            float2 f0 = __half22float2(h0), f1 = __half22float2(h1);
            rs0 += f0.x + f0.y;
            rs1 += f1.x + f1.y;
        }

#pragma unroll
        for (int kc2 = 0; kc2 < 4; kc2++) {
            const uint32_t a0 = ph[2 * kc2][0], a1 = ph[2 * kc2][1];
            const uint32_t a2 = ph[2 * kc2 + 1][0], a3 = ph[2 * kc2 + 1][1];
#pragma unroll
            for (int db2 = 0; db2 < 8; db2++) {
                uint32_t vh[4];
                ldm4(voff + db2 * 16 * VPAD + kc2 * 32, vh);
                mma_f16(oacc[2 * db2],     a0, a1, a2, a3, vh[0], vh[2]);
                mma_f16(oacc[2 * db2 + 1], a0, a1, a2, a3, vh[1], vh[3]);
            }
        }
        __syncthreads();
        stage = (stage + 1) % 3;
    }

    rs0 += __shfl_xor_sync(0xffffffff, rs0, 1);
    rs0 += __shfl_xor_sync(0xffffffff, rs0, 2);
    rs1 += __shfl_xor_sync(0xffffffff, rs1, 1);
    rs1 += __shfl_xor_sync(0xffffffff, rs1, 2);
    if ((lid & 3) == 0) {
        lp[(size_t)split * 2 * NTOK + r0g] = rs0;
        lp[(size_t)split * 2 * NTOK + NTOK + r0g] = m0;
        lp[(size_t)split * 2 * NTOK + r1g] = rs1;
        lp[(size_t)split * 2 * NTOK + NTOK + r1g] = m1;
    }
    float* mp0 = mp + ((size_t)split * NTOK + r0g) * DH;
    float* mp1 = mp + ((size_t)split * NTOK + r1g) * DH;
#pragma unroll
    for (int db = 0; db < 16; db++) {
        const int c = db * 8 + cq;
        *(float2*)(mp0 + c) = make_float2(oacc[db][0], oacc[db][1]);
        *(float2*)(mp1 + c) = make_float2(oacc[db][2], oacc[db][3]);
    }
}

// ---------------- MLP layer 1 (fused split-combine), grid 128, block 128 ----------------
__global__ void __launch_bounds__(128, 2) mlp1_kernel(
    const float* __restrict__ mp, const float* __restrict__ lp,
    const float* __restrict__ W, const float* __restrict__ bias, float* __restrict__ C)
{
    extern __shared__ float smf[];
    float* As = smf;
    float* Ws = smf + 64 * 128;
    const int tid = threadIdx.x;
    const int tx = tid & 15, ry = tid >> 4;
    const int r0 = blockIdx.x * 64;

    for (int idx = tid; idx < 64 * 32; idx += 128) {
        const int r = idx >> 5;
        const int gr = r0 + r;
        const float l0 = lp[gr], mm0 = lp[NTOK + gr];
        const float l1 = lp[2 * NTOK + gr], mm1 = lp[3 * NTOK + gr];
        const float M = fmaxf(mm0, mm1);
        const float e0 = __expf(mm0 - M), e1 = __expf(mm1 - M);
        const float inv = 1.f / (l0 * e0 + l1 * e1);
        float4 a = ((const float4*)mp)[(size_t)gr * 32 + (idx & 31)];
        float4 b = ((const float4*)mp)[(size_t)(NTOK + gr) * 32 + (idx & 31)];
        float4 r4;
        r4.x = (a.x * e0 + b.x * e1) * inv;
        r4.y = (a.y * e0 + b.y * e1) * inv;
        r4.z = (a.z * e0 + b.z * e1) * inv;
        r4.w = (a.w * e0 + b.w * e1) * inv;
        ((float4*)As)[idx] = r4;
    }

    float acc[8][8];
    gemm64_body(W, As, Ws, tid, tx, ry, acc);

#pragma unroll
    for (int i = 0; i < 8; i++) {
        float* crow = C + (size_t)(r0 + ry * 8 + i) * 128 + tx * 8;
#pragma unroll
        for (int j = 0; j < 8; j++)
            crow[j] = fmaxf(acc[i][j] + bias[tx * 8 + j], 0.f);
    }
}

// ---------------- final MLP layer, grid 128, block 128 ----------------
__global__ void __launch_bounds__(128, 2) gemm_out_kernel(
    const float* __restrict__ A, const float* __restrict__ W,
    const float* __restrict__ bias, float* __restrict__ C)
{
    extern __shared__ float smf[];
    float* As = smf;
    float* Ws = smf + 64 * 128;
    const int tid = threadIdx.x;
    const int tx = tid & 15, ry = tid >> 4;
    const int r0 = blockIdx.x * 64;

    for (int idx = tid; idx < 64 * 32; idx += 128)
        ((float4*)As)[idx] = ((const float4*)(A + (size_t)r0 * 128))[idx];

    float acc[8][8];
    gemm64_body(W, As, Ws, tid, tx, ry, acc);

#pragma unroll
    for (int i = 0; i < 8; i++) {
        float* crow = C + (size_t)(r0 + ry * 8 + i) * 128 + tx * 8;
#pragma unroll
        for (int j = 0; j < 8; j++)
            crow[j] = fmaxf(acc[i][j] + bias[tx * 8 + j], 0.f);
    }
}

// ---------------- launch ----------------
extern "C" void kernel_launch(void* const* d_in, const int* in_sizes, int n_in,
                              void* d_out, int out_size)
{
    const float* H   = (const float*)d_in[0];
    const int*   adj = (const int*)d_in[1];
    const float* Wq  = (const float*)d_in[2];
    const float* Wk  = (const float*)d_in[3];
    const float* Wv  = (const float*)d_in[4];
    const float* W1  = (const float*)d_in[5];
    const float* b1  = (const float*)d_in[6];
    const float* W2  = (const float*)d_in[7];
    const float* b2  = (const float*)d_in[8];
    float* out = (float*)d_out;

    float *mpd, *lpd, *h;
    __nv_bfloat16 *qh, *ql, *kh, *kl;
    __half *vth;
    cudaGetSymbolAddress((void**)&qh,  g_qh);
    cudaGetSymbolAddress((void**)&ql,  g_ql);
    cudaGetSymbolAddress((void**)&kh,  g_kh);
    cudaGetSymbolAddress((void**)&kl,  g_kl);
    cudaGetSymbolAddress((void**)&vth, g_vth);
    cudaGetSymbolAddress((void**)&mpd, g_mp);
    cudaGetSymbolAddress((void**)&lpd, g_lp);
    cudaGetSymbolAddress((void**)&h,   g_h);

    cudaFuncSetAttribute(attn_kernel, cudaFuncAttributeMaxDynamicSharedMemorySize, ATT_SMEM);
    cudaFuncSetAttribute(qkv_kernel, cudaFuncAttributeMaxDynamicSharedMemorySize, GSMEM);
    cudaFuncSetAttribute(mlp1_kernel, cudaFuncAttributeMaxDynamicSharedMemorySize, GSMEM);
    cudaFuncSetAttribute(gemm_out_kernel, cudaFuncAttributeMaxDynamicSharedMemorySize, GSMEM);

    qkv_kernel<<<dim3(NTOK / 64, 3), 128, GSMEM>>>(H, Wq, Wk, Wv, qh, ql, kh, kl, vth);

    attn_kernel<<<dim3(NTOK / 128, 2), 256, ATT_SMEM>>>(qh, ql, kh, kl, vth,
                                                        adj, mpd, lpd);

    mlp1_kernel<<<NTOK / 64, 128, GSMEM>>>(mpd, lpd, W1, b1, h);
    gemm_out_kernel<<<NTOK / 64, 128, GSMEM>>>(h, W2, b2, out);
}

// round 13
// speedup vs baseline: 1.2240x; 1.0891x over previous
#include <cuda_runtime.h>
#include <cuda_bf16.h>
#include <cuda_fp16.h>
#include <cstdint>

#define NTOK 8192
#define DH   128

// ---------------- scratch ----------------
__device__ __nv_bfloat16 g_qh[NTOK * DH];
__device__ __nv_bfloat16 g_ql[NTOK * DH];
__device__ __nv_bfloat16 g_kh[NTOK * DH];
__device__ __nv_bfloat16 g_kl[NTOK * DH];
__device__ __half g_vth[DH * NTOK];
__device__ float g_mp[2 * NTOK * DH];
__device__ float g_lp[4 * NTOK];
__device__ __nv_bfloat16 g_hh[NTOK * DH];
__device__ __nv_bfloat16 g_hl[NTOK * DH];
// transposed bf16 hi/lo weights [n][k]
__device__ __nv_bfloat16 g_wtqh[DH * DH], g_wtql[DH * DH];
__device__ __nv_bfloat16 g_wtkh[DH * DH], g_wtkl[DH * DH];
__device__ __nv_bfloat16 g_wtvh[DH * DH], g_wtvl[DH * DH];
__device__ __nv_bfloat16 g_wt1h[DH * DH], g_wt1l[DH * DH];
__device__ __nv_bfloat16 g_wt2h[DH * DH], g_wt2l[DH * DH];

// ---------------- helpers ----------------
__device__ __forceinline__ uint32_t smem_u32(const void* p) {
    uint32_t a;
    asm("{ .reg .u64 t; cvta.to.shared.u64 t, %1; cvt.u32.u64 %0, t; }" : "=r"(a) : "l"(p));
    return a;
}
__device__ __forceinline__ void cpa16(uint32_t dst, const void* src) {
    asm volatile("cp.async.cg.shared.global [%0], [%1], 16;" :: "r"(dst), "l"(src));
}
__device__ __forceinline__ void cpa_commit() {
    asm volatile("cp.async.commit_group;" ::: "memory");
}
template <int N>
__device__ __forceinline__ void cpa_wait() {
    asm volatile("cp.async.wait_group %0;" :: "n"(N) : "memory");
}
__device__ __forceinline__ void ldm4(uint32_t addr, uint32_t r[4]) {
    asm volatile("ldmatrix.sync.aligned.m8n8.x4.shared.b16 {%0,%1,%2,%3}, [%4];"
                 : "=r"(r[0]), "=r"(r[1]), "=r"(r[2]), "=r"(r[3]) : "r"(addr));
}
__device__ __forceinline__ void mma_bf16(float c[4], uint32_t a0, uint32_t a1,
                                         uint32_t a2, uint32_t a3,
                                         uint32_t b0, uint32_t b1) {
    asm volatile("mma.sync.aligned.m16n8k16.row.col.f32.bf16.bf16.f32 "
                 "{%0,%1,%2,%3}, {%4,%5,%6,%7}, {%8,%9}, {%0,%1,%2,%3};"
                 : "+f"(c[0]), "+f"(c[1]), "+f"(c[2]), "+f"(c[3])
                 : "r"(a0), "r"(a1), "r"(a2), "r"(a3), "r"(b0), "r"(b1));
}
__device__ __forceinline__ void mma_f16(float c[4], uint32_t a0, uint32_t a1,
                                        uint32_t a2, uint32_t a3,
                                        uint32_t b0, uint32_t b1) {
    asm volatile("mma.sync.aligned.m16n8k16.row.col.f32.f16.f16.f32 "
                 "{%0,%1,%2,%3}, {%4,%5,%6,%7}, {%8,%9}, {%0,%1,%2,%3};"
                 : "+f"(c[0]), "+f"(c[1]), "+f"(c[2]), "+f"(c[3])
                 : "r"(a0), "r"(a1), "r"(a2), "r"(a3), "r"(b0), "r"(b1));
}
__device__ __forceinline__ uint32_t pkbf(float a, float b) {
    __nv_bfloat162 t = __floats2bfloat162_rn(a, b);
    return *reinterpret_cast<uint32_t*>(&t);
}

// ---------------- weight prep: fp32 W[k][n] -> bf16 hi/lo Wt[n][k] ----------------
__global__ void __launch_bounds__(256) wprep_kernel(
    const float* __restrict__ Wq, const float* __restrict__ Wk, const float* __restrict__ Wv,
    const float* __restrict__ W1, const float* __restrict__ W2)
{
    extern __shared__ float ws[];
    const int which = blockIdx.x;
    const float* src = (which == 0) ? Wq : (which == 1) ? Wk :
                       (which == 2) ? Wv : (which == 3) ? W1 : W2;
    __nv_bfloat16* dh = (which == 0) ? g_wtqh : (which == 1) ? g_wtkh :
                        (which == 2) ? g_wtvh : (which == 3) ? g_wt1h : g_wt2h;
    __nv_bfloat16* dl = (which == 0) ? g_wtql : (which == 1) ? g_wtkl :
                        (which == 2) ? g_wtvl : (which == 3) ? g_wt1l : g_wt2l;
    for (int idx = threadIdx.x; idx < DH * DH; idx += 256) ws[idx] = src[idx];
    __syncthreads();
    for (int idx = threadIdx.x; idx < DH * DH; idx += 256) {
        const int n = idx >> 7, k = idx & 127;
        const float v = ws[k * DH + n];
        __nv_bfloat16 h = __float2bfloat16(v);
        dh[idx] = h;
        dl[idx] = __float2bfloat16(v - __bfloat162float(h));
    }
}

// ---------------- mma-GEMM body: 64 rows x 128 cols, 128 threads ----------------
// smem: A hi @0, A lo @17408, Wt hi @34816, Wt lo @69632, bias fp32 @104448
#define GKPAD 272
#define A_H 0
#define A_L 17408
#define W_H 34816
#define W_L 69632
#define BIAS_OFF 104448
#define MG_SMEM 104960

__device__ __forceinline__ void mma_gemm128(uint32_t sb, int wid, int lid, float cacc[16][4])
{
    const int lrow = lid & 15, lcol = (lid >> 4) * 8;
    const uint32_t aoff = sb + A_H + (wid * 16 + lrow) * GKPAD + lcol * 2;
    const uint32_t woff = sb + W_H + lrow * GKPAD + lcol * 2;

    uint32_t afh[8][4], afl[8][4];
#pragma unroll
    for (int kc = 0; kc < 8; kc++) {
        ldm4(aoff + kc * 32, afh[kc]);
        ldm4(aoff + (A_L - A_H) + kc * 32, afl[kc]);
    }
#pragma unroll
    for (int j = 0; j < 16; j++)
#pragma unroll
        for (int q = 0; q < 4; q++) cacc[j][q] = 0.f;

#pragma unroll
    for (int kc = 0; kc < 8; kc++) {
#pragma unroll
        for (int nb2 = 0; nb2 < 8; nb2++) {
            uint32_t wh[4], wl[4];
            ldm4(woff + nb2 * 16 * GKPAD + kc * 32, wh);
            ldm4(woff + (W_L - W_H) + nb2 * 16 * GKPAD + kc * 32, wl);
            mma_bf16(cacc[2 * nb2],     afh[kc][0], afh[kc][1], afh[kc][2], afh[kc][3], wh[0], wh[2]);
            mma_bf16(cacc[2 * nb2 + 1], afh[kc][0], afh[kc][1], afh[kc][2], afh[kc][3], wh[1], wh[3]);
            mma_bf16(cacc[2 * nb2],     afh[kc][0], afh[kc][1], afh[kc][2], afh[kc][3], wl[0], wl[2]);
            mma_bf16(cacc[2 * nb2 + 1], afh[kc][0], afh[kc][1], afh[kc][2], afh[kc][3], wl[1], wl[3]);
            mma_bf16(cacc[2 * nb2],     afl[kc][0], afl[kc][1], afl[kc][2], afl[kc][3], wh[0], wh[2]);
            mma_bf16(cacc[2 * nb2 + 1], afl[kc][0], afl[kc][1], afl[kc][2], afl[kc][3], wh[1], wh[3]);
        }
    }
}

// load Wt hi/lo into smem via cp.async (128 rows x 16 chunks of 16B, each half)
__device__ __forceinline__ void load_wt(uint32_t sb, int tid,
                                        const __nv_bfloat16* wh_g, const __nv_bfloat16* wl_g)
{
#pragma unroll
    for (int i = 0; i < 16; i++) {
        const int idx = tid + i * 128;
        const int r = idx >> 4, c = idx & 15;
        cpa16(sb + W_H + r * GKPAD + c * 16, wh_g + (size_t)r * DH + c * 8);
        cpa16(sb + W_L + r * GKPAD + c * 16, wl_g + (size_t)r * DH + c * 8);
    }
}

// ---------------- fused QKV (mma): grid (128, 3), block 128 ----------------
__global__ void __launch_bounds__(128, 1) qkv_kernel(const float* __restrict__ H)
{
    extern __shared__ char smc[];
    const uint32_t sb = smem_u32(smc);
    const int tid = threadIdx.x;
    const int wid = tid >> 5, lid = tid & 31;
    const int r0 = blockIdx.x * 64;
    const int w = blockIdx.y;

    const __nv_bfloat16* wh_g = (w == 0) ? g_wtqh : (w == 1) ? g_wtkh : g_wtvh;
    const __nv_bfloat16* wl_g = (w == 0) ? g_wtql : (w == 1) ? g_wtkl : g_wtvl;
    load_wt(sb, tid, wh_g, wl_g);
    cpa_commit();

    // A = H rows, fp32 -> bf16 hi/lo in smem
#pragma unroll
    for (int i = 0; i < 16; i++) {
        const int idx = tid + i * 128;
        const int r = idx >> 5, c4 = idx & 31;
        float4 v = ((const float4*)(H + (size_t)(r0 + r) * DH))[c4];
        __nv_bfloat16 h0 = __float2bfloat16(v.x), h1 = __float2bfloat16(v.y);
        __nv_bfloat16 h2 = __float2bfloat16(v.z), h3 = __float2bfloat16(v.w);
        __nv_bfloat162 p0 = __halves2bfloat162(h0, h1), p1 = __halves2bfloat162(h2, h3);
        *(uint2*)(smc + A_H + r * GKPAD + c4 * 8) = make_uint2(*(uint32_t*)&p0, *(uint32_t*)&p1);
        *(uint2*)(smc + A_L + r * GKPAD + c4 * 8) =
            make_uint2(pkbf(v.x - __bfloat162float(h0), v.y - __bfloat162float(h1)),
                       pkbf(v.z - __bfloat162float(h2), v.w - __bfloat162float(h3)));
    }
    cpa_wait<0>();
    __syncthreads();

    float cacc[16][4];
    mma_gemm128(sb, wid, lid, cacc);

    const int gr0 = r0 + wid * 16 + (lid >> 2);
    const int gr1 = gr0 + 8;
    const int cq = 2 * (lid & 3);

    if (w < 2) {
        __nv_bfloat16* dh = (w == 0) ? g_qh : g_kh;
        __nv_bfloat16* dl = (w == 0) ? g_ql : g_kl;
#pragma unroll
        for (int j = 0; j < 16; j++) {
            const int c = j * 8 + cq;
            {
                float v0 = cacc[j][0], v1 = cacc[j][1];
                __nv_bfloat16 h0 = __float2bfloat16(v0), h1 = __float2bfloat16(v1);
                __nv_bfloat162 hp = __halves2bfloat162(h0, h1);
                *(uint32_t*)(dh + (size_t)gr0 * DH + c) = *(uint32_t*)&hp;
                *(uint32_t*)(dl + (size_t)gr0 * DH + c) =
                    pkbf(v0 - __bfloat162float(h0), v1 - __bfloat162float(h1));
            }
            {
                float v0 = cacc[j][2], v1 = cacc[j][3];
                __nv_bfloat16 h0 = __float2bfloat16(v0), h1 = __float2bfloat16(v1);
                __nv_bfloat162 hp = __halves2bfloat162(h0, h1);
                *(uint32_t*)(dh + (size_t)gr1 * DH + c) = *(uint32_t*)&hp;
                *(uint32_t*)(dl + (size_t)gr1 * DH + c) =
                    pkbf(v0 - __bfloat162float(h0), v1 - __bfloat162float(h1));
            }
        }
    } else {
#pragma unroll
        for (int j = 0; j < 16; j++) {
            const int c = j * 8 + cq;
            g_vth[(size_t)c * NTOK + gr0]       = __float2half_rn(cacc[j][0]);
            g_vth[(size_t)(c + 1) * NTOK + gr0] = __float2half_rn(cacc[j][1]);
            g_vth[(size_t)c * NTOK + gr1]       = __float2half_rn(cacc[j][2]);
            g_vth[(size_t)(c + 1) * NTOK + gr1] = __float2half_rn(cacc[j][3]);
        }
    }
}

// ---------------- MLP layer 1 (mma, fused split-combine): grid 128 ----------------
__global__ void __launch_bounds__(128, 1) mlp1_kernel(const float* __restrict__ b1)
{
    extern __shared__ char smc[];
    const uint32_t sb = smem_u32(smc);
    float* biass = (float*)(smc + BIAS_OFF);
    const int tid = threadIdx.x;
    const int wid = tid >> 5, lid = tid & 31;
    const int r0 = blockIdx.x * 64;

    load_wt(sb, tid, g_wt1h, g_wt1l);
    cpa_commit();
    if (tid < 128) biass[tid] = b1[tid];

    // combine splits -> fp32 -> hi/lo in smem
#pragma unroll
    for (int i = 0; i < 16; i++) {
        const int idx = tid + i * 128;
        const int r = idx >> 5, c4 = idx & 31;
        const int gr = r0 + r;
        const float l0 = g_lp[gr], mm0 = g_lp[NTOK + gr];
        const float l1 = g_lp[2 * NTOK + gr], mm1 = g_lp[3 * NTOK + gr];
        const float M = fmaxf(mm0, mm1);
        const float e0 = __expf(mm0 - M), e1 = __expf(mm1 - M);
        const float inv = 1.f / (l0 * e0 + l1 * e1);
        float4 a = ((const float4*)g_mp)[(size_t)gr * 32 + c4];
        float4 b = ((const float4*)g_mp)[(size_t)(NTOK + gr) * 32 + c4];
        float4 v;
        v.x = (a.x * e0 + b.x * e1) * inv;
        v.y = (a.y * e0 + b.y * e1) * inv;
        v.z = (a.z * e0 + b.z * e1) * inv;
        v.w = (a.w * e0 + b.w * e1) * inv;
        __nv_bfloat16 h0 = __float2bfloat16(v.x), h1 = __float2bfloat16(v.y);
        __nv_bfloat16 h2 = __float2bfloat16(v.z), h3 = __float2bfloat16(v.w);
        __nv_bfloat162 p0 = __halves2bfloat162(h0, h1), p1 = __halves2bfloat162(h2, h3);
        *(uint2*)(smc + A_H + r * GKPAD + c4 * 8) = make_uint2(*(uint32_t*)&p0, *(uint32_t*)&p1);
        *(uint2*)(smc + A_L + r * GKPAD + c4 * 8) =
            make_uint2(pkbf(v.x - __bfloat162float(h0), v.y - __bfloat162float(h1)),
                       pkbf(v.z - __bfloat162float(h2), v.w - __bfloat162float(h3)));
    }
    cpa_wait<0>();
    __syncthreads();

    float cacc[16][4];
    mma_gemm128(sb, wid, lid, cacc);

    const int gr0 = r0 + wid * 16 + (lid >> 2);
    const int gr1 = gr0 + 8;
    const int cq = 2 * (lid & 3);
#pragma unroll
    for (int j = 0; j < 16; j++) {
        const int c = j * 8 + cq;
        const float bs0 = biass[c], bs1 = biass[c + 1];
        {
            float v0 = fmaxf(cacc[j][0] + bs0, 0.f), v1 = fmaxf(cacc[j][1] + bs1, 0.f);
            __nv_bfloat16 h0 = __float2bfloat16(v0), h1 = __float2bfloat16(v1);
            __nv_bfloat162 hp = __halves2bfloat162(h0, h1);
            *(uint32_t*)(g_hh + (size_t)gr0 * DH + c) = *(uint32_t*)&hp;
            *(uint32_t*)(g_hl + (size_t)gr0 * DH + c) =
                pkbf(v0 - __bfloat162float(h0), v1 - __bfloat162float(h1));
        }
        {
            float v0 = fmaxf(cacc[j][2] + bs0, 0.f), v1 = fmaxf(cacc[j][3] + bs1, 0.f);
            __nv_bfloat16 h0 = __float2bfloat16(v0), h1 = __float2bfloat16(v1);
            __nv_bfloat162 hp = __halves2bfloat162(h0, h1);
            *(uint32_t*)(g_hh + (size_t)gr1 * DH + c) = *(uint32_t*)&hp;
            *(uint32_t*)(g_hl + (size_t)gr1 * DH + c) =
                pkbf(v0 - __bfloat162float(h0), v1 - __bfloat162float(h1));
        }
    }
}

// ---------------- final MLP layer (mma): grid 128 ----------------
__global__ void __launch_bounds__(128, 1) gemm_out_kernel(
    const float* __restrict__ b2, float* __restrict__ out)
{
    extern __shared__ char smc[];
    const uint32_t sb = smem_u32(smc);
    float* biass = (float*)(smc + BIAS_OFF);
    const int tid = threadIdx.x;
    const int wid = tid >> 5, lid = tid & 31;
    const int r0 = blockIdx.x * 64;

    load_wt(sb, tid, g_wt2h, g_wt2l);
    // A = h hi/lo, already bf16: 64 rows x 16 chunks per half
#pragma unroll
    for (int i = 0; i < 8; i++) {
        const int idx = tid + i * 128;
        const int r = idx >> 4, c = idx & 15;
        cpa16(sb + A_H + r * GKPAD + c * 16, g_hh + (size_t)(r0 + r) * DH + c * 8);
        cpa16(sb + A_L + r * GKPAD + c * 16, g_hl + (size_t)(r0 + r) * DH + c * 8);
    }
    cpa_commit();
    if (tid < 128) biass[tid] = b2[tid];
    cpa_wait<0>();
    __syncthreads();

    float cacc[16][4];
    mma_gemm128(sb, wid, lid, cacc);

    const int gr0 = r0 + wid * 16 + (lid >> 2);
    const int gr1 = gr0 + 8;
    const int cq = 2 * (lid & 3);
#pragma unroll
    for (int j = 0; j < 16; j++) {
        const int c = j * 8 + cq;
        const float bs0 = biass[c], bs1 = biass[c + 1];
        *(float2*)(out + (size_t)gr0 * DH + c) =
            make_float2(fmaxf(cacc[j][0] + bs0, 0.f), fmaxf(cacc[j][1] + bs1, 0.f));
        *(float2*)(out + (size_t)gr1 * DH + c) =
            make_float2(fmaxf(cacc[j][2] + bs0, 0.f), fmaxf(cacc[j][3] + bs1, 0.f));
    }
}

// ---------------- fused attention (byte-identical to R12 best) ----------------
#define KPAD 272
#define VPAD 144
#define STG_SZ 53248
#define SK_L   17408
#define SV_H   34816
#define ATT_SMEM (3 * STG_SZ)
#define MNEG  -1e30f
#define MINIT -1e29f

__global__ void __launch_bounds__(256, 1) attn_kernel(
    const __nv_bfloat16* __restrict__ qhg, const __nv_bfloat16* __restrict__ qlg,
    const __nv_bfloat16* __restrict__ khg, const __nv_bfloat16* __restrict__ klg,
    const __half* __restrict__ vthg,
    const int* __restrict__ adj, float* __restrict__ mp, float* __restrict__ lp)
{
    extern __shared__ char smc[];
    const uint32_t sb = smem_u32(smc);
    const int tid = threadIdx.x;
    const int wid = tid >> 5, lid = tid & 31;
    const int wrow = wid * 16;
    const int qbase = blockIdx.x * 128;
    const int split = blockIdx.y;
    const int tstart = split * (NTOK / 2);
    const int ntiles = (NTOK / 2) / 64;

    const int lrow = lid & 15, lcol = (lid >> 4) * 8;
    const uint32_t kbase = sb + lrow * KPAD + lcol * 2;
    const uint32_t vbase = sb + SV_H + lrow * VPAD + lcol * 2;

    const int fr0 = wrow + (lid >> 2);
    const int r0g = qbase + fr0;
    const int r1g = r0g + 8;
    const int cq = 2 * (lid & 3);

    uint32_t qfh[8][4], qfl[8][4];
    {
        const uint32_t qoff = sb + (wrow + lrow) * KPAD + lcol * 2;
#pragma unroll
        for (int i = 0; i < 8; i++) {
            const int idx = tid + i * 256;
            const int r = idx >> 4, c = idx & 15;
            cpa16(sb + r * KPAD + c * 16, qhg + (size_t)(qbase + r) * DH + c * 8);
        }
        cpa_commit(); cpa_wait<0>(); __syncthreads();
#pragma unroll
        for (int kc = 0; kc < 8; kc++) ldm4(qoff + kc * 32, qfh[kc]);
        __syncthreads();
#pragma unroll
        for (int i = 0; i < 8; i++) {
            const int idx = tid + i * 256;
            const int r = idx >> 4, c = idx & 15;
            cpa16(sb + r * KPAD + c * 16, qlg + (size_t)(qbase + r) * DH + c * 8);
        }
        cpa_commit(); cpa_wait<0>(); __syncthreads();
#pragma unroll
        for (int kc = 0; kc < 8; kc++) ldm4(qoff + kc * 32, qfl[kc]);
        __syncthreads();
    }

#define LOAD_STAGE(stg, T0)                                                              \
    do {                                                                                 \
        const uint32_t sbase = sb + (stg) * STG_SZ;                                      \
        _Pragma("unroll")                                                                \
        for (int i = 0; i < 4; i++) {                                                    \
            const int idx = tid + i * 256;                                               \
            const int r = idx >> 4, c = idx & 15;                                        \
            cpa16(sbase + r * KPAD + c * 16,        khg + (size_t)((T0) + r) * DH + c * 8); \
            cpa16(sbase + SK_L + r * KPAD + c * 16, klg + (size_t)((T0) + r) * DH + c * 8); \
        }                                                                                \
        _Pragma("unroll")                                                                \
        for (int i = 0; i < 4; i++) {                                                    \
            const int idx = tid + i * 256;                                               \
            const int r = idx >> 3, c = idx & 7;                                         \
            cpa16(sbase + SV_H + r * VPAD + c * 16, vthg + (size_t)r * NTOK + (T0) + c * 8); \
        }                                                                                \
        cpa_commit();                                                                    \
    } while (0)

    LOAD_STAGE(0, tstart);
    LOAD_STAGE(1, tstart + 64);

    float oacc[16][4];
#pragma unroll
    for (int i = 0; i < 16; i++)
#pragma unroll
        for (int j = 0; j < 4; j++) oacc[i][j] = 0.f;
    float rs0 = 0.f, rs1 = 0.f, m0 = MINIT, m1 = MINIT;

    int stage = 0;
    for (int it = 0; it < ntiles; it++) {
        const int t0 = tstart + it * 64;

        int2 av0[8], av1[8];
#pragma unroll
        for (int nb = 0; nb < 8; nb++) {
            const int col = t0 + nb * 8 + cq;
            av0[nb] = *(const int2*)(adj + (size_t)r0g * NTOK + col);
            av1[nb] = *(const int2*)(adj + (size_t)r1g * NTOK + col);
        }

        if (it + 2 < ntiles) { LOAD_STAGE((it + 2) % 3, t0 + 128); cpa_wait<2>(); }
        else if (it + 1 < ntiles) cpa_wait<1>();
        else cpa_wait<0>();
        __syncthreads();

        uint32_t mk = 0;
#pragma unroll
        for (int nb = 0; nb < 8; nb++) {
            mk |= (av0[nb].x > 0 ? 1u : 0u) << (2 * nb);
            mk |= (av0[nb].y > 0 ? 1u : 0u) << (2 * nb + 1);
            mk |= (av1[nb].x > 0 ? 1u : 0u) << (16 + 2 * nb);
            mk |= (av1[nb].y > 0 ? 1u : 0u) << (16 + 2 * nb + 1);
        }

        const uint32_t koff = kbase + stage * STG_SZ;
        const uint32_t voff = vbase + stage * STG_SZ;

        float sacc[8][4];
#pragma unroll
        for (int i = 0; i < 8; i++)
#pragma unroll
            for (int j = 0; j < 4; j++) sacc[i][j] = 0.f;

#pragma unroll
        for (int kc = 0; kc < 8; kc++) {
#pragma unroll
            for (int nb2 = 0; nb2 < 4; nb2++) {
                uint32_t kh[4], kl[4];
                ldm4(koff + nb2 * 16 * KPAD + kc * 32, kh);
                ldm4(koff + SK_L + nb2 * 16 * KPAD + kc * 32, kl);
                mma_bf16(sacc[2 * nb2],     qfh[kc][0], qfh[kc][1], qfh[kc][2], qfh[kc][3], kh[0], kh[2]);
                mma_bf16(sacc[2 * nb2 + 1], qfh[kc][0], qfh[kc][1], qfh[kc][2], qfh[kc][3], kh[1], kh[3]);
                mma_bf16(sacc[2 * nb2],     qfh[kc][0], qfh[kc][1], qfh[kc][2], qfh[kc][3], kl[0], kl[2]);
                mma_bf16(sacc[2 * nb2 + 1], qfh[kc][0], qfh[kc][1], qfh[kc][2], qfh[kc][3], kl[1], kl[3]);
                mma_bf16(sacc[2 * nb2],     qfl[kc][0], qfl[kc][1], qfl[kc][2], qfl[kc][3], kh[0], kh[2]);
                mma_bf16(sacc[2 * nb2 + 1], qfl[kc][0], qfl[kc][1], qfl[kc][2], qfl[kc][3], kh[1], kh[3]);
            }
        }

#pragma unroll
        for (int nb = 0; nb < 8; nb++) {
            if (!((mk >> (2 * nb)) & 1))      sacc[nb][0] = MNEG;
            if (!((mk >> (2 * nb + 1)) & 1))  sacc[nb][1] = MNEG;
            if (!((mk >> (16 + 2 * nb)) & 1)) sacc[nb][2] = MNEG;
            if (!((mk >> (17 + 2 * nb)) & 1)) sacc[nb][3] = MNEG;
        }
        float tm0 = MNEG, tm1 = MNEG;
#pragma unroll
        for (int nb = 0; nb < 8; nb++) {
            tm0 = fmaxf(tm0, fmaxf(sacc[nb][0], sacc[nb][1]));
            tm1 = fmaxf(tm1, fmaxf(sacc[nb][2], sacc[nb][3]));
        }
        tm0 = fmaxf(tm0, __shfl_xor_sync(0xffffffff, tm0, 1));
        tm0 = fmaxf(tm0, __shfl_xor_sync(0xffffffff, tm0, 2));
        tm1 = fmaxf(tm1, __shfl_xor_sync(0xffffffff, tm1, 1));
        tm1 = fmaxf(tm1, __shfl_xor_sync(0xffffffff, tm1, 2));
        if (tm0 > m0) {
            const float f = __expf(m0 - tm0);
            rs0 *= f;
#pragma unroll
            for (int db = 0; db < 16; db++) { oacc[db][0] *= f; oacc[db][1] *= f; }
            m0 = tm0;
        }
        if (tm1 > m1) {
            const float f = __expf(m1 - tm1);
            rs1 *= f;
#pragma unroll
            for (int db = 0; db < 16; db++) { oacc[db][2] *= f; oacc[db][3] *= f; }
            m1 = tm1;
        }

        uint32_t ph[8][2];
#pragma unroll
        for (int nb = 0; nb < 8; nb++) {
            float p00 = __expf(sacc[nb][0] - m0);
            float p01 = __expf(sacc[nb][1] - m0);
            float p10 = __expf(sacc[nb][2] - m1);
            float p11 = __expf(sacc[nb][3] - m1);
            __half2 h0 = __floats2half2_rn(p00, p01);
            __half2 h1 = __floats2half2_rn(p10, p11);
            ph[nb][0] = *(uint32_t*)&h0;
            ph[nb][1] = *(uint32_t*)&h1;
            float2 f0 = __half22float2(h0), f1 = __half22float2(h1);
            rs0 += f0.x + f0.y;
            rs1 += f1.x + f1.y;
        }

#pragma unroll
        for (int kc2 = 0; kc2 < 4; kc2++) {
            const uint32_t a0 = ph[2 * kc2][0], a1 = ph[2 * kc2][1];
            const uint32_t a2 = ph[2 * kc2 + 1][0], a3 = ph[2 * kc2 + 1][1];
#pragma unroll
            for (int db2 = 0; db2 < 8; db2++) {
                uint32_t vh[4];
                ldm4(voff + db2 * 16 * VPAD + kc2 * 32, vh);
                mma_f16(oacc[2 * db2],     a0, a1, a2, a3, vh[0], vh[2]);
                mma_f16(oacc[2 * db2 + 1], a0, a1, a2, a3, vh[1], vh[3]);
            }
        }
        __syncthreads();
        stage = (stage + 1) % 3;
    }

    rs0 += __shfl_xor_sync(0xffffffff, rs0, 1);
    rs0 += __shfl_xor_sync(0xffffffff, rs0, 2);
    rs1 += __shfl_xor_sync(0xffffffff, rs1, 1);
    rs1 += __shfl_xor_sync(0xffffffff, rs1, 2);
    if ((lid & 3) == 0) {
        lp[(size_t)split * 2 * NTOK + r0g] = rs0;
        lp[(size_t)split * 2 * NTOK + NTOK + r0g] = m0;
        lp[(size_t)split * 2 * NTOK + r1g] = rs1;
        lp[(size_t)split * 2 * NTOK + NTOK + r1g] = m1;
    }
    float* mp0 = mp + ((size_t)split * NTOK + r0g) * DH;
    float* mp1 = mp + ((size_t)split * NTOK + r1g) * DH;
#pragma unroll
    for (int db = 0; db < 16; db++) {
        const int c = db * 8 + cq;
        *(float2*)(mp0 + c) = make_float2(oacc[db][0], oacc[db][1]);
        *(float2*)(mp1 + c) = make_float2(oacc[db][2], oacc[db][3]);
    }
}

// ---------------- launch ----------------
extern "C" void kernel_launch(void* const* d_in, const int* in_sizes, int n_in,
                              void* d_out, int out_size)
{
    const float* H   = (const float*)d_in[0];
    const int*   adj = (const int*)d_in[1];
    const float* Wq  = (const float*)d_in[2];
    const float* Wk  = (const float*)d_in[3];
    const float* Wv  = (const float*)d_in[4];
    const float* W1  = (const float*)d_in[5];
    const float* b1  = (const float*)d_in[6];
    const float* W2  = (const float*)d_in[7];
    const float* b2  = (const float*)d_in[8];
    float* out = (float*)d_out;

    float *mpd, *lpd;
    __nv_bfloat16 *qh, *ql, *kh, *kl;
    __half *vth;
    cudaGetSymbolAddress((void**)&qh,  g_qh);
    cudaGetSymbolAddress((void**)&ql,  g_ql);
    cudaGetSymbolAddress((void**)&kh,  g_kh);
    cudaGetSymbolAddress((void**)&kl,  g_kl);
    cudaGetSymbolAddress((void**)&vth, g_vth);
    cudaGetSymbolAddress((void**)&mpd, g_mp);
    cudaGetSymbolAddress((void**)&lpd, g_lp);

    cudaFuncSetAttribute(attn_kernel, cudaFuncAttributeMaxDynamicSharedMemorySize, ATT_SMEM);
    cudaFuncSetAttribute(qkv_kernel, cudaFuncAttributeMaxDynamicSharedMemorySize, MG_SMEM);
    cudaFuncSetAttribute(mlp1_kernel, cudaFuncAttributeMaxDynamicSharedMemorySize, MG_SMEM);
    cudaFuncSetAttribute(gemm_out_kernel, cudaFuncAttributeMaxDynamicSharedMemorySize, MG_SMEM);
    cudaFuncSetAttribute(wprep_kernel, cudaFuncAttributeMaxDynamicSharedMemorySize, 65536);

    wprep_kernel<<<5, 256, 65536>>>(Wq, Wk, Wv, W1, W2);

    qkv_kernel<<<dim3(NTOK / 64, 3), 128, MG_SMEM>>>(H);

    attn_kernel<<<dim3(NTOK / 128, 2), 256, ATT_SMEM>>>(qh, ql, kh, kl, vth,
                                                        adj, mpd, lpd);

    mlp1_kernel<<<NTOK / 64, 128, MG_SMEM>>>(b1);
    gemm_out_kernel<<<NTOK / 64, 128, MG_SMEM>>>(b2, out);
}

// round 14
// speedup vs baseline: 1.2478x; 1.0194x over previous
#include <cuda_runtime.h>
#include <cuda_bf16.h>
#include <cuda_fp16.h>
#include <cstdint>

#define NTOK 8192
#define DH   128

// ---------------- scratch ----------------
__device__ __nv_bfloat16 g_qh[NTOK * DH];
__device__ __nv_bfloat16 g_ql[NTOK * DH];
__device__ __nv_bfloat16 g_kh[NTOK * DH];
__device__ __nv_bfloat16 g_kl[NTOK * DH];
__device__ __half g_vth[DH * NTOK];
__device__ float g_mp[2 * NTOK * DH];
__device__ float g_lp[4 * NTOK];
__device__ __nv_bfloat16 g_hh[NTOK * DH];
__device__ __nv_bfloat16 g_hl[NTOK * DH];
// transposed bf16 hi/lo weights [n][k]
__device__ __nv_bfloat16 g_wtqh[DH * DH], g_wtql[DH * DH];
__device__ __nv_bfloat16 g_wtkh[DH * DH], g_wtkl[DH * DH];
__device__ __nv_bfloat16 g_wtvh[DH * DH], g_wtvl[DH * DH];
__device__ __nv_bfloat16 g_wt1h[DH * DH], g_wt1l[DH * DH];
__device__ __nv_bfloat16 g_wt2h[DH * DH], g_wt2l[DH * DH];

// ---------------- helpers ----------------
__device__ __forceinline__ uint32_t smem_u32(const void* p) {
    uint32_t a;
    asm("{ .reg .u64 t; cvta.to.shared.u64 t, %1; cvt.u32.u64 %0, t; }" : "=r"(a) : "l"(p));
    return a;
}
__device__ __forceinline__ void cpa16(uint32_t dst, const void* src) {
    asm volatile("cp.async.cg.shared.global [%0], [%1], 16;" :: "r"(dst), "l"(src));
}
__device__ __forceinline__ void cpa_commit() {
    asm volatile("cp.async.commit_group;" ::: "memory");
}
template <int N>
__device__ __forceinline__ void cpa_wait() {
    asm volatile("cp.async.wait_group %0;" :: "n"(N) : "memory");
}
__device__ __forceinline__ void ldm4(uint32_t addr, uint32_t r[4]) {
    asm volatile("ldmatrix.sync.aligned.m8n8.x4.shared.b16 {%0,%1,%2,%3}, [%4];"
                 : "=r"(r[0]), "=r"(r[1]), "=r"(r[2]), "=r"(r[3]) : "r"(addr));
}
__device__ __forceinline__ void mma_bf16(float c[4], uint32_t a0, uint32_t a1,
                                         uint32_t a2, uint32_t a3,
                                         uint32_t b0, uint32_t b1) {
    asm volatile("mma.sync.aligned.m16n8k16.row.col.f32.bf16.bf16.f32 "
                 "{%0,%1,%2,%3}, {%4,%5,%6,%7}, {%8,%9}, {%0,%1,%2,%3};"
                 : "+f"(c[0]), "+f"(c[1]), "+f"(c[2]), "+f"(c[3])
                 : "r"(a0), "r"(a1), "r"(a2), "r"(a3), "r"(b0), "r"(b1));
}
__device__ __forceinline__ void mma_f16(float c[4], uint32_t a0, uint32_t a1,
                                        uint32_t a2, uint32_t a3,
                                        uint32_t b0, uint32_t b1) {
    asm volatile("mma.sync.aligned.m16n8k16.row.col.f32.f16.f16.f32 "
                 "{%0,%1,%2,%3}, {%4,%5,%6,%7}, {%8,%9}, {%0,%1,%2,%3};"
                 : "+f"(c[0]), "+f"(c[1]), "+f"(c[2]), "+f"(c[3])
                 : "r"(a0), "r"(a1), "r"(a2), "r"(a3), "r"(b0), "r"(b1));
}
__device__ __forceinline__ uint32_t pkbf(float a, float b) {
    __nv_bfloat162 t = __floats2bfloat162_rn(a, b);
    return *reinterpret_cast<uint32_t*>(&t);
}

// ---------------- weight prep: fp32 W[k][n] -> bf16 hi/lo Wt[n][k] ----------------
__global__ void __launch_bounds__(256) wprep_kernel(
    const float* __restrict__ Wq, const float* __restrict__ Wk, const float* __restrict__ Wv,
    const float* __restrict__ W1, const float* __restrict__ W2)
{
    extern __shared__ float ws[];
    const int which = blockIdx.x;
    const float* src = (which == 0) ? Wq : (which == 1) ? Wk :
                       (which == 2) ? Wv : (which == 3) ? W1 : W2;
    __nv_bfloat16* dh = (which == 0) ? g_wtqh : (which == 1) ? g_wtkh :
                        (which == 2) ? g_wtvh : (which == 3) ? g_wt1h : g_wt2h;
    __nv_bfloat16* dl = (which == 0) ? g_wtql : (which == 1) ? g_wtkl :
                        (which == 2) ? g_wtvl : (which == 3) ? g_wt1l : g_wt2l;
    for (int idx = threadIdx.x; idx < DH * DH; idx += 256) ws[idx] = src[idx];
    __syncthreads();
    for (int idx = threadIdx.x; idx < DH * DH; idx += 256) {
        const int n = idx >> 7, k = idx & 127;
        const float v = ws[k * DH + n];
        __nv_bfloat16 h = __float2bfloat16(v);
        dh[idx] = h;
        dl[idx] = __float2bfloat16(v - __bfloat162float(h));
    }
}

// ---------------- mma-GEMM body: 64 rows x 128 cols, 256 threads ----------------
// 8 warps: warp w -> row group (w>>1)*16, N-half (w&1)*64. 192 MMAs/warp.
#define GKPAD 272
#define A_H 0
#define A_L 17408
#define W_H 34816
#define W_L 69632
#define BIAS_OFF 104448
#define MG_SMEM 104960

__device__ __forceinline__ void mma_gemm256(uint32_t sb, int wid, int lid, float cacc[8][4])
{
    const int g = wid >> 1, hn = wid & 1;
    const int lrow = lid & 15, lcol = (lid >> 4) * 8;
    const uint32_t aoff = sb + A_H + (g * 16 + lrow) * GKPAD + lcol * 2;
    const uint32_t woff = sb + W_H + (hn * 64 + lrow) * GKPAD + lcol * 2;

    uint32_t afh[8][4], afl[8][4];
#pragma unroll
    for (int kc = 0; kc < 8; kc++) {
        ldm4(aoff + kc * 32, afh[kc]);
        ldm4(aoff + (A_L - A_H) + kc * 32, afl[kc]);
    }
#pragma unroll
    for (int j = 0; j < 8; j++)
#pragma unroll
        for (int q = 0; q < 4; q++) cacc[j][q] = 0.f;

#pragma unroll
    for (int kc = 0; kc < 8; kc++) {
#pragma unroll
        for (int nb2 = 0; nb2 < 4; nb2++) {
            uint32_t wh[4], wl[4];
            ldm4(woff + nb2 * 16 * GKPAD + kc * 32, wh);
            ldm4(woff + (W_L - W_H) + nb2 * 16 * GKPAD + kc * 32, wl);
            mma_bf16(cacc[2 * nb2],     afh[kc][0], afh[kc][1], afh[kc][2], afh[kc][3], wh[0], wh[2]);
            mma_bf16(cacc[2 * nb2 + 1], afh[kc][0], afh[kc][1], afh[kc][2], afh[kc][3], wh[1], wh[3]);
            mma_bf16(cacc[2 * nb2],     afh[kc][0], afh[kc][1], afh[kc][2], afh[kc][3], wl[0], wl[2]);
            mma_bf16(cacc[2 * nb2 + 1], afh[kc][0], afh[kc][1], afh[kc][2], afh[kc][3], wl[1], wl[3]);
            mma_bf16(cacc[2 * nb2],     afl[kc][0], afl[kc][1], afl[kc][2], afl[kc][3], wh[0], wh[2]);
            mma_bf16(cacc[2 * nb2 + 1], afl[kc][0], afl[kc][1], afl[kc][2], afl[kc][3], wh[1], wh[3]);
        }
    }
}

// load Wt hi/lo into smem via cp.async (256 threads)
__device__ __forceinline__ void load_wt(uint32_t sb, int tid,
                                        const __nv_bfloat16* wh_g, const __nv_bfloat16* wl_g)
{
#pragma unroll
    for (int i = 0; i < 8; i++) {
        const int idx = tid + i * 256;
        const int r = idx >> 4, c = idx & 15;
        cpa16(sb + W_H + r * GKPAD + c * 16, wh_g + (size_t)r * DH + c * 8);
        cpa16(sb + W_L + r * GKPAD + c * 16, wl_g + (size_t)r * DH + c * 8);
    }
}

// ---------------- fused QKV (mma): grid (128, 3), block 256 ----------------
__global__ void __launch_bounds__(256, 1) qkv_kernel(const float* __restrict__ H)
{
    extern __shared__ char smc[];
    const uint32_t sb = smem_u32(smc);
    const int tid = threadIdx.x;
    const int wid = tid >> 5, lid = tid & 31;
    const int r0 = blockIdx.x * 64;
    const int w = blockIdx.y;

    const __nv_bfloat16* wh_g = (w == 0) ? g_wtqh : (w == 1) ? g_wtkh : g_wtvh;
    const __nv_bfloat16* wl_g = (w == 0) ? g_wtql : (w == 1) ? g_wtkl : g_wtvl;
    load_wt(sb, tid, wh_g, wl_g);
    cpa_commit();

    // A = H rows, fp32 -> bf16 hi/lo in smem
#pragma unroll
    for (int i = 0; i < 8; i++) {
        const int idx = tid + i * 256;
        const int r = idx >> 5, c4 = idx & 31;
        float4 v = ((const float4*)(H + (size_t)(r0 + r) * DH))[c4];
        __nv_bfloat16 h0 = __float2bfloat16(v.x), h1 = __float2bfloat16(v.y);
        __nv_bfloat16 h2 = __float2bfloat16(v.z), h3 = __float2bfloat16(v.w);
        __nv_bfloat162 p0 = __halves2bfloat162(h0, h1), p1 = __halves2bfloat162(h2, h3);
        *(uint2*)(smc + A_H + r * GKPAD + c4 * 8) = make_uint2(*(uint32_t*)&p0, *(uint32_t*)&p1);
        *(uint2*)(smc + A_L + r * GKPAD + c4 * 8) =
            make_uint2(pkbf(v.x - __bfloat162float(h0), v.y - __bfloat162float(h1)),
                       pkbf(v.z - __bfloat162float(h2), v.w - __bfloat162float(h3)));
    }
    cpa_wait<0>();
    __syncthreads();

    float cacc[8][4];
    mma_gemm256(sb, wid, lid, cacc);

    const int gr0 = r0 + (wid >> 1) * 16 + (lid >> 2);
    const int gr1 = gr0 + 8;
    const int cbase = (wid & 1) * 64;
    const int cq = 2 * (lid & 3);

    if (w < 2) {
        __nv_bfloat16* dh = (w == 0) ? g_qh : g_kh;
        __nv_bfloat16* dl = (w == 0) ? g_ql : g_kl;
#pragma unroll
        for (int j = 0; j < 8; j++) {
            const int c = cbase + j * 8 + cq;
            {
                float v0 = cacc[j][0], v1 = cacc[j][1];
                __nv_bfloat16 h0 = __float2bfloat16(v0), h1 = __float2bfloat16(v1);
                __nv_bfloat162 hp = __halves2bfloat162(h0, h1);
                *(uint32_t*)(dh + (size_t)gr0 * DH + c) = *(uint32_t*)&hp;
                *(uint32_t*)(dl + (size_t)gr0 * DH + c) =
                    pkbf(v0 - __bfloat162float(h0), v1 - __bfloat162float(h1));
            }
            {
                float v0 = cacc[j][2], v1 = cacc[j][3];
                __nv_bfloat16 h0 = __float2bfloat16(v0), h1 = __float2bfloat16(v1);
                __nv_bfloat162 hp = __halves2bfloat162(h0, h1);
                *(uint32_t*)(dh + (size_t)gr1 * DH + c) = *(uint32_t*)&hp;
                *(uint32_t*)(dl + (size_t)gr1 * DH + c) =
                    pkbf(v0 - __bfloat162float(h0), v1 - __bfloat162float(h1));
            }
        }
    } else {
#pragma unroll
        for (int j = 0; j < 8; j++) {
            const int c = cbase + j * 8 + cq;
            g_vth[(size_t)c * NTOK + gr0]       = __float2half_rn(cacc[j][0]);
            g_vth[(size_t)(c + 1) * NTOK + gr0] = __float2half_rn(cacc[j][1]);
            g_vth[(size_t)c * NTOK + gr1]       = __float2half_rn(cacc[j][2]);
            g_vth[(size_t)(c + 1) * NTOK + gr1] = __float2half_rn(cacc[j][3]);
        }
    }
}

// ---------------- MLP layer 1 (mma, fused split-combine): grid 128, block 256 ----------------
__global__ void __launch_bounds__(256, 1) mlp1_kernel(const float* __restrict__ b1)
{
    extern __shared__ char smc[];
    const uint32_t sb = smem_u32(smc);
    float* biass = (float*)(smc + BIAS_OFF);
    const int tid = threadIdx.x;
    const int wid = tid >> 5, lid = tid & 31;
    const int r0 = blockIdx.x * 64;

    load_wt(sb, tid, g_wt1h, g_wt1l);
    cpa_commit();
    if (tid < 128) biass[tid] = b1[tid];

    // combine splits -> fp32 -> hi/lo in smem
#pragma unroll
    for (int i = 0; i < 8; i++) {
        const int idx = tid + i * 256;
        const int r = idx >> 5, c4 = idx & 31;
        const int gr = r0 + r;
        const float l0 = g_lp[gr], mm0 = g_lp[NTOK + gr];
        const float l1 = g_lp[2 * NTOK + gr], mm1 = g_lp[3 * NTOK + gr];
        const float M = fmaxf(mm0, mm1);
        const float e0 = __expf(mm0 - M), e1 = __expf(mm1 - M);
        const float inv = 1.f / (l0 * e0 + l1 * e1);
        float4 a = ((const float4*)g_mp)[(size_t)gr * 32 + c4];
        float4 b = ((const float4*)g_mp)[(size_t)(NTOK + gr) * 32 + c4];
        float4 v;
        v.x = (a.x * e0 + b.x * e1) * inv;
        v.y = (a.y * e0 + b.y * e1) * inv;
        v.z = (a.z * e0 + b.z * e1) * inv;
        v.w = (a.w * e0 + b.w * e1) * inv;
        __nv_bfloat16 h0 = __float2bfloat16(v.x), h1 = __float2bfloat16(v.y);
        __nv_bfloat16 h2 = __float2bfloat16(v.z), h3 = __float2bfloat16(v.w);
        __nv_bfloat162 p0 = __halves2bfloat162(h0, h1), p1 = __halves2bfloat162(h2, h3);
        *(uint2*)(smc + A_H + r * GKPAD + c4 * 8) = make_uint2(*(uint32_t*)&p0, *(uint32_t*)&p1);
        *(uint2*)(smc + A_L + r * GKPAD + c4 * 8) =
            make_uint2(pkbf(v.x - __bfloat162float(h0), v.y - __bfloat162float(h1)),
                       pkbf(v.z - __bfloat162float(h2), v.w - __bfloat162float(h3)));
    }
    cpa_wait<0>();
    __syncthreads();

    float cacc[8][4];
    mma_gemm256(sb, wid, lid, cacc);

    const int gr0 = r0 + (wid >> 1) * 16 + (lid >> 2);
    const int gr1 = gr0 + 8;
    const int cbase = (wid & 1) * 64;
    const int cq = 2 * (lid & 3);
#pragma unroll
    for (int j = 0; j < 8; j++) {
        const int c = cbase + j * 8 + cq;
        const float bs0 = biass[c], bs1 = biass[c + 1];
        {
            float v0 = fmaxf(cacc[j][0] + bs0, 0.f), v1 = fmaxf(cacc[j][1] + bs1, 0.f);
            __nv_bfloat16 h0 = __float2bfloat16(v0), h1 = __float2bfloat16(v1);
            __nv_bfloat162 hp = __halves2bfloat162(h0, h1);
            *(uint32_t*)(g_hh + (size_t)gr0 * DH + c) = *(uint32_t*)&hp;
            *(uint32_t*)(g_hl + (size_t)gr0 * DH + c) =
                pkbf(v0 - __bfloat162float(h0), v1 - __bfloat162float(h1));
        }
        {
            float v0 = fmaxf(cacc[j][2] + bs0, 0.f), v1 = fmaxf(cacc[j][3] + bs1, 0.f);
            __nv_bfloat16 h0 = __float2bfloat16(v0), h1 = __float2bfloat16(v1);
            __nv_bfloat162 hp = __halves2bfloat162(h0, h1);
            *(uint32_t*)(g_hh + (size_t)gr1 * DH + c) = *(uint32_t*)&hp;
            *(uint32_t*)(g_hl + (size_t)gr1 * DH + c) =
                pkbf(v0 - __bfloat162float(h0), v1 - __bfloat162float(h1));
        }
    }
}

// ---------------- final MLP layer (mma): grid 128, block 256 ----------------
__global__ void __launch_bounds__(256, 1) gemm_out_kernel(
    const float* __restrict__ b2, float* __restrict__ out)
{
    extern __shared__ char smc[];
    const uint32_t sb = smem_u32(smc);
    float* biass = (float*)(smc + BIAS_OFF);
    const int tid = threadIdx.x;
    const int wid = tid >> 5, lid = tid & 31;
    const int r0 = blockIdx.x * 64;

    load_wt(sb, tid, g_wt2h, g_wt2l);
#pragma unroll
    for (int i = 0; i < 4; i++) {
        const int idx = tid + i * 256;
        const int r = idx >> 4, c = idx & 15;
        cpa16(sb + A_H + r * GKPAD + c * 16, g_hh + (size_t)(r0 + r) * DH + c * 8);
        cpa16(sb + A_L + r * GKPAD + c * 16, g_hl + (size_t)(r0 + r) * DH + c * 8);
    }
    cpa_commit();
    if (tid < 128) biass[tid] = b2[tid];
    cpa_wait<0>();
    __syncthreads();

    float cacc[8][4];
    mma_gemm256(sb, wid, lid, cacc);

    const int gr0 = r0 + (wid >> 1) * 16 + (lid >> 2);
    const int gr1 = gr0 + 8;
    const int cbase = (wid & 1) * 64;
    const int cq = 2 * (lid & 3);
#pragma unroll
    for (int j = 0; j < 8; j++) {
        const int c = cbase + j * 8 + cq;
        const float bs0 = biass[c], bs1 = biass[c + 1];
        *(float2*)(out + (size_t)gr0 * DH + c) =
            make_float2(fmaxf(cacc[j][0] + bs0, 0.f), fmaxf(cacc[j][1] + bs1, 0.f));
        *(float2*)(out + (size_t)gr1 * DH + c) =
            make_float2(fmaxf(cacc[j][2] + bs0, 0.f), fmaxf(cacc[j][3] + bs1, 0.f));
    }
}

// ---------------- fused attention (byte-identical to R13 best) ----------------
#define KPAD 272
#define VPAD 144
#define STG_SZ 53248
#define SK_L   17408
#define SV_H   34816
#define ATT_SMEM (3 * STG_SZ)
#define MNEG  -1e30f
#define MINIT -1e29f

__global__ void __launch_bounds__(256, 1) attn_kernel(
    const __nv_bfloat16* __restrict__ qhg, const __nv_bfloat16* __restrict__ qlg,
    const __nv_bfloat16* __restrict__ khg, const __nv_bfloat16* __restrict__ klg,
    const __half* __restrict__ vthg,
    const int* __restrict__ adj, float* __restrict__ mp, float* __restrict__ lp)
{
    extern __shared__ char smc[];
    const uint32_t sb = smem_u32(smc);
    const int tid = threadIdx.x;
    const int wid = tid >> 5, lid = tid & 31;
    const int wrow = wid * 16;
    const int qbase = blockIdx.x * 128;
    const int split = blockIdx.y;
    const int tstart = split * (NTOK / 2);
    const int ntiles = (NTOK / 2) / 64;

    const int lrow = lid & 15, lcol = (lid >> 4) * 8;
    const uint32_t kbase = sb + lrow * KPAD + lcol * 2;
    const uint32_t vbase = sb + SV_H + lrow * VPAD + lcol * 2;

    const int fr0 = wrow + (lid >> 2);
    const int r0g = qbase + fr0;
    const int r1g = r0g + 8;
    const int cq = 2 * (lid & 3);

    uint32_t qfh[8][4], qfl[8][4];
    {
        const uint32_t qoff = sb + (wrow + lrow) * KPAD + lcol * 2;
#pragma unroll
        for (int i = 0; i < 8; i++) {
            const int idx = tid + i * 256;
            const int r = idx >> 4, c = idx & 15;
            cpa16(sb + r * KPAD + c * 16, qhg + (size_t)(qbase + r) * DH + c * 8);
        }
        cpa_commit(); cpa_wait<0>(); __syncthreads();
#pragma unroll
        for (int kc = 0; kc < 8; kc++) ldm4(qoff + kc * 32, qfh[kc]);
        __syncthreads();
#pragma unroll
        for (int i = 0; i < 8; i++) {
            const int idx = tid + i * 256;
            const int r = idx >> 4, c = idx & 15;
            cpa16(sb + r * KPAD + c * 16, qlg + (size_t)(qbase + r) * DH + c * 8);
        }
        cpa_commit(); cpa_wait<0>(); __syncthreads();
#pragma unroll
        for (int kc = 0; kc < 8; kc++) ldm4(qoff + kc * 32, qfl[kc]);
        __syncthreads();
    }

#define LOAD_STAGE(stg, T0)                                                              \
    do {                                                                                 \
        const uint32_t sbase = sb + (stg) * STG_SZ;                                      \
        _Pragma("unroll")                                                                \
        for (int i = 0; i < 4; i++) {                                                    \
            const int idx = tid + i * 256;                                               \
            const int r = idx >> 4, c = idx & 15;                                        \
            cpa16(sbase + r * KPAD + c * 16,        khg + (size_t)((T0) + r) * DH + c * 8); \
            cpa16(sbase + SK_L + r * KPAD + c * 16, klg + (size_t)((T0) + r) * DH + c * 8); \
        }                                                                                \
        _Pragma("unroll")                                                                \
        for (int i = 0; i < 4; i++) {                                                    \
            const int idx = tid + i * 256;                                               \
            const int r = idx >> 3, c = idx & 7;                                         \
            cpa16(sbase + SV_H + r * VPAD + c * 16, vthg + (size_t)r * NTOK + (T0) + c * 8); \
        }                                                                                \
        cpa_commit();                                                                    \
    } while (0)

    LOAD_STAGE(0, tstart);
    LOAD_STAGE(1, tstart + 64);

    float oacc[16][4];
#pragma unroll
    for (int i = 0; i < 16; i++)
#pragma unroll
        for (int j = 0; j < 4; j++) oacc[i][j] = 0.f;
    float rs0 = 0.f, rs1 = 0.f, m0 = MINIT, m1 = MINIT;

    int stage = 0;
    for (int it = 0; it < ntiles; it++) {
        const int t0 = tstart + it * 64;

        int2 av0[8], av1[8];
#pragma unroll
        for (int nb = 0; nb < 8; nb++) {
            const int col = t0 + nb * 8 + cq;
            av0[nb] = *(const int2*)(adj + (size_t)r0g * NTOK + col);
            av1[nb] = *(const int2*)(adj + (size_t)r1g * NTOK + col);
        }

        if (it + 2 < ntiles) { LOAD_STAGE((it + 2) % 3, t0 + 128); cpa_wait<2>(); }
        else if (it + 1 < ntiles) cpa_wait<1>();
        else cpa_wait<0>();
        __syncthreads();

        uint32_t mk = 0;
#pragma unroll
        for (int nb = 0; nb < 8; nb++) {
            mk |= (av0[nb].x > 0 ? 1u : 0u) << (2 * nb);
            mk |= (av0[nb].y > 0 ? 1u : 0u) << (2 * nb + 1);
            mk |= (av1[nb].x > 0 ? 1u : 0u) << (16 + 2 * nb);
            mk |= (av1[nb].y > 0 ? 1u : 0u) << (16 + 2 * nb + 1);
        }

        const uint32_t koff = kbase + stage * STG_SZ;
        const uint32_t voff = vbase + stage * STG_SZ;

        float sacc[8][4];
#pragma unroll
        for (int i = 0; i < 8; i++)
#pragma unroll
            for (int j = 0; j < 4; j++) sacc[i][j] = 0.f;

#pragma unroll
        for (int kc = 0; kc < 8; kc++) {
#pragma unroll
            for (int nb2 = 0; nb2 < 4; nb2++) {
                uint32_t kh[4], kl[4];
                ldm4(koff + nb2 * 16 * KPAD + kc * 32, kh);
                ldm4(koff + SK_L + nb2 * 16 * KPAD + kc * 32, kl);
                mma_bf16(sacc[2 * nb2],     qfh[kc][0], qfh[kc][1], qfh[kc][2], qfh[kc][3], kh[0], kh[2]);
                mma_bf16(sacc[2 * nb2 + 1], qfh[kc][0], qfh[kc][1], qfh[kc][2], qfh[kc][3], kh[1], kh[3]);
                mma_bf16(sacc[2 * nb2],     qfh[kc][0], qfh[kc][1], qfh[kc][2], qfh[kc][3], kl[0], kl[2]);
                mma_bf16(sacc[2 * nb2 + 1], qfh[kc][0], qfh[kc][1], qfh[kc][2], qfh[kc][3], kl[1], kl[3]);
                mma_bf16(sacc[2 * nb2],     qfl[kc][0], qfl[kc][1], qfl[kc][2], qfl[kc][3], kh[0], kh[2]);
                mma_bf16(sacc[2 * nb2 + 1], qfl[kc][0], qfl[kc][1], qfl[kc][2], qfl[kc][3], kh[1], kh[3]);
            }
        }

#pragma unroll
        for (int nb = 0; nb < 8; nb++) {
            if (!((mk >> (2 * nb)) & 1))      sacc[nb][0] = MNEG;
            if (!((mk >> (2 * nb + 1)) & 1))  sacc[nb][1] = MNEG;
            if (!((mk >> (16 + 2 * nb)) & 1)) sacc[nb][2] = MNEG;
            if (!((mk >> (17 + 2 * nb)) & 1)) sacc[nb][3] = MNEG;
        }
        float tm0 = MNEG, tm1 = MNEG;
#pragma unroll
        for (int nb = 0; nb < 8; nb++) {
            tm0 = fmaxf(tm0, fmaxf(sacc[nb][0], sacc[nb][1]));
            tm1 = fmaxf(tm1, fmaxf(sacc[nb][2], sacc[nb][3]));
        }
        tm0 = fmaxf(tm0, __shfl_xor_sync(0xffffffff, tm0, 1));
        tm0 = fmaxf(tm0, __shfl_xor_sync(0xffffffff, tm0, 2));
        tm1 = fmaxf(tm1, __shfl_xor_sync(0xffffffff, tm1, 1));
        tm1 = fmaxf(tm1, __shfl_xor_sync(0xffffffff, tm1, 2));
        if (tm0 > m0) {
            const float f = __expf(m0 - tm0);
            rs0 *= f;
#pragma unroll
            for (int db = 0; db < 16; db++) { oacc[db][0] *= f; oacc[db][1] *= f; }
            m0 = tm0;
        }
        if (tm1 > m1) {
            const float f = __expf(m1 - tm1);
            rs1 *= f;
#pragma unroll
            for (int db = 0; db < 16; db++) { oacc[db][2] *= f; oacc[db][3] *= f; }
            m1 = tm1;
        }

        uint32_t ph[8][2];
#pragma unroll
        for (int nb = 0; nb < 8; nb++) {
            float p00 = __expf(sacc[nb][0] - m0);
            float p01 = __expf(sacc[nb][1] - m0);
            float p10 = __expf(sacc[nb][2] - m1);
            float p11 = __expf(sacc[nb][3] - m1);
            __half2 h0 = __floats2half2_rn(p00, p01);
            __half2 h1 = __floats2half2_rn(p10, p11);
            ph[nb][0] = *(uint32_t*)&h0;
            ph[nb][1] = *(uint32_t*)&h1;
            float2 f0 = __half22float2(h0), f1 = __half22float2(h1);
            rs0 += f0.x + f0.y;
            rs1 += f1.x + f1.y;
        }

#pragma unroll
        for (int kc2 = 0; kc2 < 4; kc2++) {
            const uint32_t a0 = ph[2 * kc2][0], a1 = ph[2 * kc2][1];
            const uint32_t a2 = ph[2 * kc2 + 1][0], a3 = ph[2 * kc2 + 1][1];
#pragma unroll
            for (int db2 = 0; db2 < 8; db2++) {
                uint32_t vh[4];
                ldm4(voff + db2 * 16 * VPAD + kc2 * 32, vh);
                mma_f16(oacc[2 * db2],     a0, a1, a2, a3, vh[0], vh[2]);
                mma_f16(oacc[2 * db2 + 1], a0, a1, a2, a3, vh[1], vh[3]);
            }
        }
        __syncthreads();
        stage = (stage + 1) % 3;
    }

    rs0 += __shfl_xor_sync(0xffffffff, rs0, 1);
    rs0 += __shfl_xor_sync(0xffffffff, rs0, 2);
    rs1 += __shfl_xor_sync(0xffffffff, rs1, 1);
    rs1 += __shfl_xor_sync(0xffffffff, rs1, 2);
    if ((lid & 3) == 0) {
        lp[(size_t)split * 2 * NTOK + r0g] = rs0;
        lp[(size_t)split * 2 * NTOK + NTOK + r0g] = m0;
        lp[(size_t)split * 2 * NTOK + r1g] = rs1;
        lp[(size_t)split * 2 * NTOK + NTOK + r1g] = m1;
    }
    float* mp0 = mp + ((size_t)split * NTOK + r0g) * DH;
    float* mp1 = mp + ((size_t)split * NTOK + r1g) * DH;
#pragma unroll
    for (int db = 0; db < 16; db++) {
        const int c = db * 8 + cq;
        *(float2*)(mp0 + c) = make_float2(oacc[db][0], oacc[db][1]);
        *(float2*)(mp1 + c) = make_float2(oacc[db][2], oacc[db][3]);
    }
}

// ---------------- launch ----------------
extern "C" void kernel_launch(void* const* d_in, const int* in_sizes, int n_in,
                              void* d_out, int out_size)
{
    const float* H   = (const float*)d_in[0];
    const int*   adj = (const int*)d_in[1];
    const float* Wq  = (const float*)d_in[2];
    const float* Wk  = (const float*)d_in[3];
    const float* Wv  = (const float*)d_in[4];
    const float* W1  = (const float*)d_in[5];
    const float* b1  = (const float*)d_in[6];
    const float* W2  = (const float*)d_in[7];
    const float* b2  = (const float*)d_in[8];
    float* out = (float*)d_out;

    float *mpd, *lpd;
    __nv_bfloat16 *qh, *ql, *kh, *kl;
    __half *vth;
    cudaGetSymbolAddress((void**)&qh,  g_qh);
    cudaGetSymbolAddress((void**)&ql,  g_ql);
    cudaGetSymbolAddress((void**)&kh,  g_kh);
    cudaGetSymbolAddress((void**)&kl,  g_kl);
    cudaGetSymbolAddress((void**)&vth, g_vth);
    cudaGetSymbolAddress((void**)&mpd, g_mp);
    cudaGetSymbolAddress((void**)&lpd, g_lp);

    cudaFuncSetAttribute(attn_kernel, cudaFuncAttributeMaxDynamicSharedMemorySize, ATT_SMEM);
    cudaFuncSetAttribute(qkv_kernel, cudaFuncAttributeMaxDynamicSharedMemorySize, MG_SMEM);
    cudaFuncSetAttribute(mlp1_kernel, cudaFuncAttributeMaxDynamicSharedMemorySize, MG_SMEM);
    cudaFuncSetAttribute(gemm_out_kernel, cudaFuncAttributeMaxDynamicSharedMemorySize, MG_SMEM);
    cudaFuncSetAttribute(wprep_kernel, cudaFuncAttributeMaxDynamicSharedMemorySize, 65536);

    wprep_kernel<<<5, 256, 65536>>>(Wq, Wk, Wv, W1, W2);

    qkv_kernel<<<dim3(NTOK / 64, 3), 256, MG_SMEM>>>(H);

    attn_kernel<<<dim3(NTOK / 128, 2), 256, ATT_SMEM>>>(qh, ql, kh, kl, vth,
                                                        adj, mpd, lpd);

    mlp1_kernel<<<NTOK / 64, 256, MG_SMEM>>>(b1);
    gemm_out_kernel<<<NTOK / 64, 256, MG_SMEM>>>(b2, out);
}

// round 15
// speedup vs baseline: 1.2567x; 1.0071x over previous
#include <cuda_runtime.h>
#include <cuda_bf16.h>
#include <cuda_fp16.h>
#include <cstdint>

#define NTOK 8192
#define DH   128

// ---------------- scratch ----------------
__device__ __nv_bfloat16 g_qh[NTOK * DH];
__device__ __nv_bfloat16 g_ql[NTOK * DH];
__device__ __nv_bfloat16 g_kh[NTOK * DH];
__device__ __nv_bfloat16 g_kl[NTOK * DH];
__device__ __half g_vth[DH * NTOK];
__device__ float g_mp[2 * NTOK * DH];
__device__ float g_lp[4 * NTOK];
// transposed bf16 hi/lo weights [n][k]
__device__ __nv_bfloat16 g_wtqh[DH * DH], g_wtql[DH * DH];
__device__ __nv_bfloat16 g_wtkh[DH * DH], g_wtkl[DH * DH];
__device__ __nv_bfloat16 g_wtvh[DH * DH], g_wtvl[DH * DH];
__device__ __nv_bfloat16 g_wt1h[DH * DH], g_wt1l[DH * DH];
__device__ __nv_bfloat16 g_wt2h[DH * DH], g_wt2l[DH * DH];

// ---------------- helpers ----------------
__device__ __forceinline__ uint32_t smem_u32(const void* p) {
    uint32_t a;
    asm("{ .reg .u64 t; cvta.to.shared.u64 t, %1; cvt.u32.u64 %0, t; }" : "=r"(a) : "l"(p));
    return a;
}
__device__ __forceinline__ void cpa16(uint32_t dst, const void* src) {
    asm volatile("cp.async.cg.shared.global [%0], [%1], 16;" :: "r"(dst), "l"(src));
}
__device__ __forceinline__ void cpa_commit() {
    asm volatile("cp.async.commit_group;" ::: "memory");
}
template <int N>
__device__ __forceinline__ void cpa_wait() {
    asm volatile("cp.async.wait_group %0;" :: "n"(N) : "memory");
}
__device__ __forceinline__ void ldm4(uint32_t addr, uint32_t r[4]) {
    asm volatile("ldmatrix.sync.aligned.m8n8.x4.shared.b16 {%0,%1,%2,%3}, [%4];"
                 : "=r"(r[0]), "=r"(r[1]), "=r"(r[2]), "=r"(r[3]) : "r"(addr));
}
__device__ __forceinline__ void mma_bf16(float c[4], uint32_t a0, uint32_t a1,
                                         uint32_t a2, uint32_t a3,
                                         uint32_t b0, uint32_t b1) {
    asm volatile("mma.sync.aligned.m16n8k16.row.col.f32.bf16.bf16.f32 "
                 "{%0,%1,%2,%3}, {%4,%5,%6,%7}, {%8,%9}, {%0,%1,%2,%3};"
                 : "+f"(c[0]), "+f"(c[1]), "+f"(c[2]), "+f"(c[3])
                 : "r"(a0), "r"(a1), "r"(a2), "r"(a3), "r"(b0), "r"(b1));
}
__device__ __forceinline__ void mma_f16(float c[4], uint32_t a0, uint32_t a1,
                                        uint32_t a2, uint32_t a3,
                                        uint32_t b0, uint32_t b1) {
    asm volatile("mma.sync.aligned.m16n8k16.row.col.f32.f16.f16.f32 "
                 "{%0,%1,%2,%3}, {%4,%5,%6,%7}, {%8,%9}, {%0,%1,%2,%3};"
                 : "+f"(c[0]), "+f"(c[1]), "+f"(c[2]), "+f"(c[3])
                 : "r"(a0), "r"(a1), "r"(a2), "r"(a3), "r"(b0), "r"(b1));
}
__device__ __forceinline__ uint32_t pkbf(float a, float b) {
    __nv_bfloat162 t = __floats2bfloat162_rn(a, b);
    return *reinterpret_cast<uint32_t*>(&t);
}

// ---------------- weight prep: fp32 W[k][n] -> bf16 hi/lo Wt[n][k] ----------------
__global__ void __launch_bounds__(256) wprep_kernel(
    const float* __restrict__ Wq, const float* __restrict__ Wk, const float* __restrict__ Wv,
    const float* __restrict__ W1, const float* __restrict__ W2)
{
    extern __shared__ float ws[];
    const int which = blockIdx.x;
    const float* src = (which == 0) ? Wq : (which == 1) ? Wk :
                       (which == 2) ? Wv : (which == 3) ? W1 : W2;
    __nv_bfloat16* dh = (which == 0) ? g_wtqh : (which == 1) ? g_wtkh :
                        (which == 2) ? g_wtvh : (which == 3) ? g_wt1h : g_wt2h;
    __nv_bfloat16* dl = (which == 0) ? g_wtql : (which == 1) ? g_wtkl :
                        (which == 2) ? g_wtvl : (which == 3) ? g_wt1l : g_wt2l;
    for (int idx = threadIdx.x; idx < DH * DH; idx += 256) ws[idx] = src[idx];
    __syncthreads();
    for (int idx = threadIdx.x; idx < DH * DH; idx += 256) {
        const int n = idx >> 7, k = idx & 127;
        const float v = ws[k * DH + n];
        __nv_bfloat16 h = __float2bfloat16(v);
        dh[idx] = h;
        dl[idx] = __float2bfloat16(v - __bfloat162float(h));
    }
}

// ---------------- mma-GEMM body: 64 rows x 128 cols, 256 threads ----------------
// 8 warps: warp w -> row group (w>>1)*16, N-half (w&1)*64. 192 MMAs/warp.
// A lo at a_base+17408, W lo at w_base+34816.
#define GKPAD 272
#define ADELTA 17408
#define WDELTA 34816

__device__ __forceinline__ void mma_gemm256(uint32_t sb, int wid, int lid, float cacc[8][4],
                                            uint32_t a_base, uint32_t w_base)
{
    const int g = wid >> 1, hn = wid & 1;
    const int lrow = lid & 15, lcol = (lid >> 4) * 8;
    const uint32_t aoff = sb + a_base + (g * 16 + lrow) * GKPAD + lcol * 2;
    const uint32_t woff = sb + w_base + (hn * 64 + lrow) * GKPAD + lcol * 2;

    uint32_t afh[8][4], afl[8][4];
#pragma unroll
    for (int kc = 0; kc < 8; kc++) {
        ldm4(aoff + kc * 32, afh[kc]);
        ldm4(aoff + ADELTA + kc * 32, afl[kc]);
    }
#pragma unroll
    for (int j = 0; j < 8; j++)
#pragma unroll
        for (int q = 0; q < 4; q++) cacc[j][q] = 0.f;

#pragma unroll
    for (int kc = 0; kc < 8; kc++) {
#pragma unroll
        for (int nbp = 0; nbp < 2; nbp++) {
            uint32_t wa[4], la[4], wb[4], lb[4];
            const uint32_t oa = woff + (2 * nbp) * 16 * GKPAD + kc * 32;
            const uint32_t ob = woff + (2 * nbp + 1) * 16 * GKPAD + kc * 32;
            ldm4(oa, wa); ldm4(oa + WDELTA, la);
            ldm4(ob, wb); ldm4(ob + WDELTA, lb);
            mma_bf16(cacc[4 * nbp + 0], afh[kc][0], afh[kc][1], afh[kc][2], afh[kc][3], wa[0], wa[2]);
            mma_bf16(cacc[4 * nbp + 1], afh[kc][0], afh[kc][1], afh[kc][2], afh[kc][3], wa[1], wa[3]);
            mma_bf16(cacc[4 * nbp + 2], afh[kc][0], afh[kc][1], afh[kc][2], afh[kc][3], wb[0], wb[2]);
            mma_bf16(cacc[4 * nbp + 3], afh[kc][0], afh[kc][1], afh[kc][2], afh[kc][3], wb[1], wb[3]);
            mma_bf16(cacc[4 * nbp + 0], afh[kc][0], afh[kc][1], afh[kc][2], afh[kc][3], la[0], la[2]);
            mma_bf16(cacc[4 * nbp + 1], afh[kc][0], afh[kc][1], afh[kc][2], afh[kc][3], la[1], la[3]);
            mma_bf16(cacc[4 * nbp + 2], afh[kc][0], afh[kc][1], afh[kc][2], afh[kc][3], lb[0], lb[2]);
            mma_bf16(cacc[4 * nbp + 3], afh[kc][0], afh[kc][1], afh[kc][2], afh[kc][3], lb[1], lb[3]);
            mma_bf16(cacc[4 * nbp + 0], afl[kc][0], afl[kc][1], afl[kc][2], afl[kc][3], wa[0], wa[2]);
            mma_bf16(cacc[4 * nbp + 1], afl[kc][0], afl[kc][1], afl[kc][2], afl[kc][3], wa[1], wa[3]);
            mma_bf16(cacc[4 * nbp + 2], afl[kc][0], afl[kc][1], afl[kc][2], afl[kc][3], wb[0], wb[2]);
            mma_bf16(cacc[4 * nbp + 3], afl[kc][0], afl[kc][1], afl[kc][2], afl[kc][3], wb[1], wb[3]);
        }
    }
}

// load a Wt hi/lo pair into smem at dst_base (hi) / dst_base+WDELTA (lo)
__device__ __forceinline__ void load_wt(uint32_t sb, int tid, uint32_t dst_base,
                                        const __nv_bfloat16* wh_g, const __nv_bfloat16* wl_g)
{
#pragma unroll
    for (int i = 0; i < 8; i++) {
        const int idx = tid + i * 256;
        const int r = idx >> 4, c = idx & 15;
        cpa16(sb + dst_base + r * GKPAD + c * 16, wh_g + (size_t)r * DH + c * 8);
        cpa16(sb + dst_base + WDELTA + r * GKPAD + c * 16, wl_g + (size_t)r * DH + c * 8);
    }
}

// ---------------- fused QKV (mma): grid (128, 3), block 256 ----------------
#define QKV_W 34816
#define QKV_SMEM 104448

__global__ void __launch_bounds__(256, 1) qkv_kernel(const float* __restrict__ H)
{
    extern __shared__ char smc[];
    const uint32_t sb = smem_u32(smc);
    const int tid = threadIdx.x;
    const int wid = tid >> 5, lid = tid & 31;
    const int r0 = blockIdx.x * 64;
    const int w = blockIdx.y;

    const __nv_bfloat16* wh_g = (w == 0) ? g_wtqh : (w == 1) ? g_wtkh : g_wtvh;
    const __nv_bfloat16* wl_g = (w == 0) ? g_wtql : (w == 1) ? g_wtkl : g_wtvl;
    load_wt(sb, tid, QKV_W, wh_g, wl_g);
    cpa_commit();

    // A = H rows, fp32 -> bf16 hi/lo in smem
#pragma unroll
    for (int i = 0; i < 8; i++) {
        const int idx = tid + i * 256;
        const int r = idx >> 5, c4 = idx & 31;
        float4 v = ((const float4*)(H + (size_t)(r0 + r) * DH))[c4];
        __nv_bfloat16 h0 = __float2bfloat16(v.x), h1 = __float2bfloat16(v.y);
        __nv_bfloat16 h2 = __float2bfloat16(v.z), h3 = __float2bfloat16(v.w);
        __nv_bfloat162 p0 = __halves2bfloat162(h0, h1), p1 = __halves2bfloat162(h2, h3);
        *(uint2*)(smc + r * GKPAD + c4 * 8) = make_uint2(*(uint32_t*)&p0, *(uint32_t*)&p1);
        *(uint2*)(smc + ADELTA + r * GKPAD + c4 * 8) =
            make_uint2(pkbf(v.x - __bfloat162float(h0), v.y - __bfloat162float(h1)),
                       pkbf(v.z - __bfloat162float(h2), v.w - __bfloat162float(h3)));
    }
    cpa_wait<0>();
    __syncthreads();

    float cacc[8][4];
    mma_gemm256(sb, wid, lid, cacc, 0, QKV_W);

    const int gr0 = r0 + (wid >> 1) * 16 + (lid >> 2);
    const int gr1 = gr0 + 8;
    const int cbase = (wid & 1) * 64;
    const int cq = 2 * (lid & 3);

    if (w < 2) {
        __nv_bfloat16* dh = (w == 0) ? g_qh : g_kh;
        __nv_bfloat16* dl = (w == 0) ? g_ql : g_kl;
#pragma unroll
        for (int j = 0; j < 8; j++) {
            const int c = cbase + j * 8 + cq;
            {
                float v0 = cacc[j][0], v1 = cacc[j][1];
                __nv_bfloat16 h0 = __float2bfloat16(v0), h1 = __float2bfloat16(v1);
                __nv_bfloat162 hp = __halves2bfloat162(h0, h1);
                *(uint32_t*)(dh + (size_t)gr0 * DH + c) = *(uint32_t*)&hp;
                *(uint32_t*)(dl + (size_t)gr0 * DH + c) =
                    pkbf(v0 - __bfloat162float(h0), v1 - __bfloat162float(h1));
            }
            {
                float v0 = cacc[j][2], v1 = cacc[j][3];
                __nv_bfloat16 h0 = __float2bfloat16(v0), h1 = __float2bfloat16(v1);
                __nv_bfloat162 hp = __halves2bfloat162(h0, h1);
                *(uint32_t*)(dh + (size_t)gr1 * DH + c) = *(uint32_t*)&hp;
                *(uint32_t*)(dl + (size_t)gr1 * DH + c) =
                    pkbf(v0 - __bfloat162float(h0), v1 - __bfloat162float(h1));
            }
        }
    } else {
#pragma unroll
        for (int j = 0; j < 8; j++) {
            const int c = cbase + j * 8 + cq;
            g_vth[(size_t)c * NTOK + gr0]       = __float2half_rn(cacc[j][0]);
            g_vth[(size_t)(c + 1) * NTOK + gr0] = __float2half_rn(cacc[j][1]);
            g_vth[(size_t)c * NTOK + gr1]       = __float2half_rn(cacc[j][2]);
            g_vth[(size_t)(c + 1) * NTOK + gr1] = __float2half_rn(cacc[j][3]);
        }
    }
}

// ---------------- merged MLP (combine + GEMM1 + ReLU + GEMM2): grid 128 ----------------
#define M2_W1 34816
#define M2_W2 104448
#define M2_B1 174080
#define M2_B2 174592
#define M2_SMEM 175104

__global__ void __launch_bounds__(256, 1) mlp_kernel(
    const float* __restrict__ b1, const float* __restrict__ b2, float* __restrict__ out)
{
    extern __shared__ char smc[];
    const uint32_t sb = smem_u32(smc);
    float* b1s = (float*)(smc + M2_B1);
    float* b2s = (float*)(smc + M2_B2);
    const int tid = threadIdx.x;
    const int wid = tid >> 5, lid = tid & 31;
    const int r0 = blockIdx.x * 64;

    load_wt(sb, tid, M2_W1, g_wt1h, g_wt1l);
    load_wt(sb, tid, M2_W2, g_wt2h, g_wt2l);
    cpa_commit();
    if (tid < 128) { b1s[tid] = b1[tid]; b2s[tid] = b2[tid]; }

    // combine splits -> fp32 -> A hi/lo in smem
#pragma unroll
    for (int i = 0; i < 8; i++) {
        const int idx = tid + i * 256;
        const int r = idx >> 5, c4 = idx & 31;
        const int gr = r0 + r;
        const float l0 = g_lp[gr], mm0 = g_lp[NTOK + gr];
        const float l1 = g_lp[2 * NTOK + gr], mm1 = g_lp[3 * NTOK + gr];
        const float M = fmaxf(mm0, mm1);
        const float e0 = __expf(mm0 - M), e1 = __expf(mm1 - M);
        const float inv = 1.f / (l0 * e0 + l1 * e1);
        float4 a = ((const float4*)g_mp)[(size_t)gr * 32 + c4];
        float4 b = ((const float4*)g_mp)[(size_t)(NTOK + gr) * 32 + c4];
        float4 v;
        v.x = (a.x * e0 + b.x * e1) * inv;
        v.y = (a.y * e0 + b.y * e1) * inv;
        v.z = (a.z * e0 + b.z * e1) * inv;
        v.w = (a.w * e0 + b.w * e1) * inv;
        __nv_bfloat16 h0 = __float2bfloat16(v.x), h1 = __float2bfloat16(v.y);
        __nv_bfloat16 h2 = __float2bfloat16(v.z), h3 = __float2bfloat16(v.w);
        __nv_bfloat162 p0 = __halves2bfloat162(h0, h1), p1 = __halves2bfloat162(h2, h3);
        *(uint2*)(smc + r * GKPAD + c4 * 8) = make_uint2(*(uint32_t*)&p0, *(uint32_t*)&p1);
        *(uint2*)(smc + ADELTA + r * GKPAD + c4 * 8) =
            make_uint2(pkbf(v.x - __bfloat162float(h0), v.y - __bfloat162float(h1)),
                       pkbf(v.z - __bfloat162float(h2), v.w - __bfloat162float(h3)));
    }
    cpa_wait<0>();
    __syncthreads();

    float cacc[8][4];
    mma_gemm256(sb, wid, lid, cacc, 0, M2_W1);
    __syncthreads();   // all warps done reading A fragments

    const int lr0 = (wid >> 1) * 16 + (lid >> 2);
    const int lr1 = lr0 + 8;
    const int cbase = (wid & 1) * 64;
    const int cq = 2 * (lid & 3);

    // h = relu(GEMM1 + b1) -> A region (hi/lo bf16), then GEMM2
#pragma unroll
    for (int j = 0; j < 8; j++) {
        const int c = cbase + j * 8 + cq;
        const float bs0 = b1s[c], bs1 = b1s[c + 1];
        {
            float v0 = fmaxf(cacc[j][0] + bs0, 0.f), v1 = fmaxf(cacc[j][1] + bs1, 0.f);
            __nv_bfloat16 h0 = __float2bfloat16(v0), h1 = __float2bfloat16(v1);
            __nv_bfloat162 hp = __halves2bfloat162(h0, h1);
            *(uint32_t*)(smc + lr0 * GKPAD + c * 2) = *(uint32_t*)&hp;
            *(uint32_t*)(smc + ADELTA + lr0 * GKPAD + c * 2) =
                pkbf(v0 - __bfloat162float(h0), v1 - __bfloat162float(h1));
        }
        {
            float v0 = fmaxf(cacc[j][2] + bs0, 0.f), v1 = fmaxf(cacc[j][3] + bs1, 0.f);
            __nv_bfloat16 h0 = __float2bfloat16(v0), h1 = __float2bfloat16(v1);
            __nv_bfloat162 hp = __halves2bfloat162(h0, h1);
            *(uint32_t*)(smc + lr1 * GKPAD + c * 2) = *(uint32_t*)&hp;
            *(uint32_t*)(smc + ADELTA + lr1 * GKPAD + c * 2) =
                pkbf(v0 - __bfloat162float(h0), v1 - __bfloat162float(h1));
        }
    }
    __syncthreads();

    mma_gemm256(sb, wid, lid, cacc, 0, M2_W2);

#pragma unroll
    for (int j = 0; j < 8; j++) {
        const int c = cbase + j * 8 + cq;
        const float bs0 = b2s[c], bs1 = b2s[c + 1];
        *(float2*)(out + (size_t)(r0 + lr0) * DH + c) =
            make_float2(fmaxf(cacc[j][0] + bs0, 0.f), fmaxf(cacc[j][1] + bs1, 0.f));
        *(float2*)(out + (size_t)(r0 + lr1) * DH + c) =
            make_float2(fmaxf(cacc[j][2] + bs0, 0.f), fmaxf(cacc[j][3] + bs1, 0.f));
    }
}

// ---------------- fused attention (S-MMA reordered; numerics identical) ----------------
#define KPAD 272
#define VPAD 144
#define STG_SZ 53248
#define SK_L   17408
#define SV_H   34816
#define ATT_SMEM (3 * STG_SZ)
#define MNEG  -1e30f
#define MINIT -1e29f

__global__ void __launch_bounds__(256, 1) attn_kernel(
    const __nv_bfloat16* __restrict__ qhg, const __nv_bfloat16* __restrict__ qlg,
    const __nv_bfloat16* __restrict__ khg, const __nv_bfloat16* __restrict__ klg,
    const __half* __restrict__ vthg,
    const int* __restrict__ adj, float* __restrict__ mp, float* __restrict__ lp)
{
    extern __shared__ char smc[];
    const uint32_t sb = smem_u32(smc);
    const int tid = threadIdx.x;
    const int wid = tid >> 5, lid = tid & 31;
    const int wrow = wid * 16;
    const int qbase = blockIdx.x * 128;
    const int split = blockIdx.y;
    const int tstart = split * (NTOK / 2);
    const int ntiles = (NTOK / 2) / 64;

    const int lrow = lid & 15, lcol = (lid >> 4) * 8;
    const uint32_t kbase = sb + lrow * KPAD + lcol * 2;
    const uint32_t vbase = sb + SV_H + lrow * VPAD + lcol * 2;

    const int fr0 = wrow + (lid >> 2);
    const int r0g = qbase + fr0;
    const int r1g = r0g + 8;
    const int cq = 2 * (lid & 3);

    uint32_t qfh[8][4], qfl[8][4];
    {
        const uint32_t qoff = sb + (wrow + lrow) * KPAD + lcol * 2;
#pragma unroll
        for (int i = 0; i < 8; i++) {
            const int idx = tid + i * 256;
            const int r = idx >> 4, c = idx & 15;
            cpa16(sb + r * KPAD + c * 16, qhg + (size_t)(qbase + r) * DH + c * 8);
        }
        cpa_commit(); cpa_wait<0>(); __syncthreads();
#pragma unroll
        for (int kc = 0; kc < 8; kc++) ldm4(qoff + kc * 32, qfh[kc]);
        __syncthreads();
#pragma unroll
        for (int i = 0; i < 8; i++) {
            const int idx = tid + i * 256;
            const int r = idx >> 4, c = idx & 15;
            cpa16(sb + r * KPAD + c * 16, qlg + (size_t)(qbase + r) * DH + c * 8);
        }
        cpa_commit(); cpa_wait<0>(); __syncthreads();
#pragma unroll
        for (int kc = 0; kc < 8; kc++) ldm4(qoff + kc * 32, qfl[kc]);
        __syncthreads();
    }

#define LOAD_STAGE(stg, T0)                                                              \
    do {                                                                                 \
        const uint32_t sbase = sb + (stg) * STG_SZ;                                      \
        _Pragma("unroll")                                                                \
        for (int i = 0; i < 4; i++) {                                                    \
            const int idx = tid + i * 256;                                               \
            const int r = idx >> 4, c = idx & 15;                                        \
            cpa16(sbase + r * KPAD + c * 16,        khg + (size_t)((T0) + r) * DH + c * 8); \
            cpa16(sbase + SK_L + r * KPAD + c * 16, klg + (size_t)((T0) + r) * DH + c * 8); \
        }                                                                                \
        _Pragma("unroll")                                                                \
        for (int i = 0; i < 4; i++) {                                                    \
            const int idx = tid + i * 256;                                               \
            const int r = idx >> 3, c = idx & 7;                                         \
            cpa16(sbase + SV_H + r * VPAD + c * 16, vthg + (size_t)r * NTOK + (T0) + c * 8); \
        }                                                                                \
        cpa_commit();                                                                    \
    } while (0)

    LOAD_STAGE(0, tstart);
    LOAD_STAGE(1, tstart + 64);

    float oacc[16][4];
#pragma unroll
    for (int i = 0; i < 16; i++)
#pragma unroll
        for (int j = 0; j < 4; j++) oacc[i][j] = 0.f;
    float rs0 = 0.f, rs1 = 0.f, m0 = MINIT, m1 = MINIT;

    int stage = 0;
    for (int it = 0; it < ntiles; it++) {
        const int t0 = tstart + it * 64;

        int2 av0[8], av1[8];
#pragma unroll
        for (int nb = 0; nb < 8; nb++) {
            const int col = t0 + nb * 8 + cq;
            av0[nb] = *(const int2*)(adj + (size_t)r0g * NTOK + col);
            av1[nb] = *(const int2*)(adj + (size_t)r1g * NTOK + col);
        }

        if (it + 2 < ntiles) { LOAD_STAGE((it + 2) % 3, t0 + 128); cpa_wait<2>(); }
        else if (it + 1 < ntiles) cpa_wait<1>();
        else cpa_wait<0>();
        __syncthreads();

        uint32_t mk = 0;
#pragma unroll
        for (int nb = 0; nb < 8; nb++) {
            mk |= (av0[nb].x > 0 ? 1u : 0u) << (2 * nb);
            mk |= (av0[nb].y > 0 ? 1u : 0u) << (2 * nb + 1);
            mk |= (av1[nb].x > 0 ? 1u : 0u) << (16 + 2 * nb);
            mk |= (av1[nb].y > 0 ? 1u : 0u) << (16 + 2 * nb + 1);
        }

        const uint32_t koff = kbase + stage * STG_SZ;
        const uint32_t voff = vbase + stage * STG_SZ;

        // ---- S = Q K^T, term-major over nb2-pairs (acc reuse distance 4;
        //      per-accumulator order hh, hl, lh preserved -> bit-identical) ----
        float sacc[8][4];
#pragma unroll
        for (int i = 0; i < 8; i++)
#pragma unroll
            for (int j = 0; j < 4; j++) sacc[i][j] = 0.f;

#pragma unroll
        for (int kc = 0; kc < 8; kc++) {
#pragma unroll
            for (int nbp = 0; nbp < 2; nbp++) {
                uint32_t ka[4], la[4], kb[4], lb[4];
                const uint32_t oa = koff + (2 * nbp) * 16 * KPAD + kc * 32;
                const uint32_t ob = koff + (2 * nbp + 1) * 16 * KPAD + kc * 32;
                ldm4(oa, ka); ldm4(oa + SK_L, la);
                ldm4(ob, kb); ldm4(ob + SK_L, lb);
                mma_bf16(sacc[4 * nbp + 0], qfh[kc][0], qfh[kc][1], qfh[kc][2], qfh[kc][3], ka[0], ka[2]);
                mma_bf16(sacc[4 * nbp + 1], qfh[kc][0], qfh[kc][1], qfh[kc][2], qfh[kc][3], ka[1], ka[3]);
                mma_bf16(sacc[4 * nbp + 2], qfh[kc][0], qfh[kc][1], qfh[kc][2], qfh[kc][3], kb[0], kb[2]);
                mma_bf16(sacc[4 * nbp + 3], qfh[kc][0], qfh[kc][1], qfh[kc][2], qfh[kc][3], kb[1], kb[3]);
                mma_bf16(sacc[4 * nbp + 0], qfh[kc][0], qfh[kc][1], qfh[kc][2], qfh[kc][3], la[0], la[2]);
                mma_bf16(sacc[4 * nbp + 1], qfh[kc][0], qfh[kc][1], qfh[kc][2], qfh[kc][3], la[1], la[3]);
                mma_bf16(sacc[4 * nbp + 2], qfh[kc][0], qfh[kc][1], qfh[kc][2], qfh[kc][3], lb[0], lb[2]);
                mma_bf16(sacc[4 * nbp + 3], qfh[kc][0], qfh[kc][1], qfh[kc][2], qfh[kc][3], lb[1], lb[3]);
                mma_bf16(sacc[4 * nbp + 0], qfl[kc][0], qfl[kc][1], qfl[kc][2], qfl[kc][3], ka[0], ka[2]);
                mma_bf16(sacc[4 * nbp + 1], qfl[kc][0], qfl[kc][1], qfl[kc][2], qfl[kc][3], ka[1], ka[3]);
                mma_bf16(sacc[4 * nbp + 2], qfl[kc][0], qfl[kc][1], qfl[kc][2], qfl[kc][3], kb[0], kb[2]);
                mma_bf16(sacc[4 * nbp + 3], qfl[kc][0], qfl[kc][1], qfl[kc][2], qfl[kc][3], kb[1], kb[3]);
            }
        }

#pragma unroll
        for (int nb = 0; nb < 8; nb++) {
            if (!((mk >> (2 * nb)) & 1))      sacc[nb][0] = MNEG;
            if (!((mk >> (2 * nb + 1)) & 1))  sacc[nb][1] = MNEG;
            if (!((mk >> (16 + 2 * nb)) & 1)) sacc[nb][2] = MNEG;
            if (!((mk >> (17 + 2 * nb)) & 1)) sacc[nb][3] = MNEG;
        }
        float tm0 = MNEG, tm1 = MNEG;
#pragma unroll
        for (int nb = 0; nb < 8; nb++) {
            tm0 = fmaxf(tm0, fmaxf(sacc[nb][0], sacc[nb][1]));
            tm1 = fmaxf(tm1, fmaxf(sacc[nb][2], sacc[nb][3]));
        }
        tm0 = fmaxf(tm0, __shfl_xor_sync(0xffffffff, tm0, 1));
        tm0 = fmaxf(tm0, __shfl_xor_sync(0xffffffff, tm0, 2));
        tm1 = fmaxf(tm1, __shfl_xor_sync(0xffffffff, tm1, 1));
        tm1 = fmaxf(tm1, __shfl_xor_sync(0xffffffff, tm1, 2));
        if (tm0 > m0) {
            const float f = __expf(m0 - tm0);
            rs0 *= f;
#pragma unroll
            for (int db = 0; db < 16; db++) { oacc[db][0] *= f; oacc[db][1] *= f; }
            m0 = tm0;
        }
        if (tm1 > m1) {
            const float f = __expf(m1 - tm1);
            rs1 *= f;
#pragma unroll
            for (int db = 0; db < 16; db++) { oacc[db][2] *= f; oacc[db][3] *= f; }
            m1 = tm1;
        }

        uint32_t ph[8][2];
#pragma unroll
        for (int nb = 0; nb < 8; nb++) {
            float p00 = __expf(sacc[nb][0] - m0);
            float p01 = __expf(sacc[nb][1] - m0);
            float p10 = __expf(sacc[nb][2] - m1);
            float p11 = __expf(sacc[nb][3] - m1);
            __half2 h0 = __floats2half2_rn(p00, p01);
            __half2 h1 = __floats2half2_rn(p10, p11);
            ph[nb][0] = *(uint32_t*)&h0;
            ph[nb][1] = *(uint32_t*)&h1;
            float2 f0 = __half22float2(h0), f1 = __half22float2(h1);
            rs0 += f0.x + f0.y;
            rs1 += f1.x + f1.y;
        }

#pragma unroll
        for (int kc2 = 0; kc2 < 4; kc2++) {
            const uint32_t a0 = ph[2 * kc2][0], a1 = ph[2 * kc2][1];
            const uint32_t a2 = ph[2 * kc2 + 1][0], a3 = ph[2 * kc2 + 1][1];
#pragma unroll
            for (int db2 = 0; db2 < 8; db2++) {
                uint32_t vh[4];
                ldm4(voff + db2 * 16 * VPAD + kc2 * 32, vh);
                mma_f16(oacc[2 * db2],     a0, a1, a2, a3, vh[0], vh[2]);
                mma_f16(oacc[2 * db2 + 1], a0, a1, a2, a3, vh[1], vh[3]);
            }
        }
        __syncthreads();
        stage = (stage + 1) % 3;
    }

    rs0 += __shfl_xor_sync(0xffffffff, rs0, 1);
    rs0 += __shfl_xor_sync(0xffffffff, rs0, 2);
    rs1 += __shfl_xor_sync(0xffffffff, rs1, 1);
    rs1 += __shfl_xor_sync(0xffffffff, rs1, 2);
    if ((lid & 3) == 0) {
        lp[(size_t)split * 2 * NTOK + r0g] = rs0;
        lp[(size_t)split * 2 * NTOK + NTOK + r0g] = m0;
        lp[(size_t)split * 2 * NTOK + r1g] = rs1;
        lp[(size_t)split * 2 * NTOK + NTOK + r1g] = m1;
    }
    float* mp0 = mp + ((size_t)split * NTOK + r0g) * DH;
    float* mp1 = mp + ((size_t)split * NTOK + r1g) * DH;
#pragma unroll
    for (int db = 0; db < 16; db++) {
        const int c = db * 8 + cq;
        *(float2*)(mp0 + c) = make_float2(oacc[db][0], oacc[db][1]);
        *(float2*)(mp1 + c) = make_float2(oacc[db][2], oacc[db][3]);
    }
}

// ---------------- launch ----------------
extern "C" void kernel_launch(void* const* d_in, const int* in_sizes, int n_in,
                              void* d_out, int out_size)
{
    const float* H   = (const float*)d_in[0];
    const int*   adj = (const int*)d_in[1];
    const float* Wq  = (const float*)d_in[2];
    const float* Wk  = (const float*)d_in[3];
    const float* Wv  = (const float*)d_in[4];
    const float* W1  = (const float*)d_in[5];
    const float* b1  = (const float*)d_in[6];
    const float* W2  = (const float*)d_in[7];
    const float* b2  = (const float*)d_in[8];
    float* out = (float*)d_out;

    float *mpd, *lpd;
    __nv_bfloat16 *qh, *ql, *kh, *kl;
    __half *vth;
    cudaGetSymbolAddress((void**)&qh,  g_qh);
    cudaGetSymbolAddress((void**)&ql,  g_ql);
    cudaGetSymbolAddress((void**)&kh,  g_kh);
    cudaGetSymbolAddress((void**)&kl,  g_kl);
    cudaGetSymbolAddress((void**)&vth, g_vth);
    cudaGetSymbolAddress((void**)&mpd, g_mp);
    cudaGetSymbolAddress((void**)&lpd, g_lp);

    cudaFuncSetAttribute(attn_kernel, cudaFuncAttributeMaxDynamicSharedMemorySize, ATT_SMEM);
    cudaFuncSetAttribute(qkv_kernel, cudaFuncAttributeMaxDynamicSharedMemorySize, QKV_SMEM);
    cudaFuncSetAttribute(mlp_kernel, cudaFuncAttributeMaxDynamicSharedMemorySize, M2_SMEM);
    cudaFuncSetAttribute(wprep_kernel, cudaFuncAttributeMaxDynamicSharedMemorySize, 65536);

    wprep_kernel<<<5, 256, 65536>>>(Wq, Wk, Wv, W1, W2);

    qkv_kernel<<<dim3(NTOK / 64, 3), 256, QKV_SMEM>>>(H);

    attn_kernel<<<dim3(NTOK / 128, 2), 256, ATT_SMEM>>>(qh, ql, kh, kl, vth,
                                                        adj, mpd, lpd);

    mlp_kernel<<<NTOK / 64, 256, M2_SMEM>>>(b1, b2, out);
}